// round 11
// baseline (speedup 1.0000x reference)
#include <cuda_runtime.h>
#include <cuda_bf16.h>
#include <cstdint>
#include <math.h>

#define BATCH 8192
#define IN1   49
#define HID   256
#define NCOEF 13
#define KP1   704      // 49*14 = 686, padded to 64-multiple
#define K2    3584     // 256*14
#define OUT3  10

// ================= helpers (baseline PTX only: sm_80-era features) =================
__device__ __forceinline__ uint32_t smem_to_u32(const void* p) {
    uint32_t a;
    asm("{ .reg .u64 t; cvta.to.shared.u64 t, %1; cvt.u32.u64 %0, t; }" : "=r"(a) : "l"(p));
    return a;
}

#define CP16(dst, src) \
    asm volatile("cp.async.cg.shared.global [%0], [%1], 16;" :: "r"(dst), "l"(src) : "memory")
#define CP_COMMIT() asm volatile("cp.async.commit_group;" ::: "memory")
#define CP_WAIT2()  asm volatile("cp.async.wait_group 2;" ::: "memory")
#define CP_WAIT1()  asm volatile("cp.async.wait_group 1;" ::: "memory")
#define CP_WAIT0()  asm volatile("cp.async.wait_group 0;" ::: "memory")

#define LDSM4(r, addr) \
    asm volatile("ldmatrix.sync.aligned.m8n8.x4.shared.b16 {%0,%1,%2,%3}, [%4];" \
        : "=r"((r)[0]), "=r"((r)[1]), "=r"((r)[2]), "=r"((r)[3]) : "r"(addr))

#define MMA_BF16(d, a, b0, b1) \
    asm volatile("mma.sync.aligned.m16n8k16.row.col.f32.bf16.bf16.f32 " \
        "{%0,%1,%2,%3},{%4,%5,%6,%7},{%8,%9},{%0,%1,%2,%3};" \
        : "+f"((d)[0]), "+f"((d)[1]), "+f"((d)[2]), "+f"((d)[3]) \
        : "r"((a)[0]), "r"((a)[1]), "r"((a)[2]), "r"((a)[3]), "r"(b0), "r"(b1))

// ================= scratch =================
__device__ float         g_H [BATCH * HID];   // layer-1 output
__device__ float         g_H2[BATCH * HID];   // layer-2 output
__device__ __nv_bfloat16 g_Ah[(size_t)BATCH * KP1];
__device__ __nv_bfloat16 g_Al[(size_t)BATCH * KP1];
__device__ __nv_bfloat16 g_Wh1[HID * KP1];
__device__ __nv_bfloat16 g_Wl1[HID * KP1];
__device__ __nv_bfloat16 g_Wh2[HID * K2];
__device__ __nv_bfloat16 g_Wl2[HID * K2];
__device__ float         g_W3[K2 * OUT3];

// ================= shared KAN math =================
__device__ __forceinline__ float mish_f(float xv) {
    float sp = fmaxf(xv, 0.f) + log1pf(expf(-fabsf(xv)));
    return xv * tanhf(sp);
}

// basis only (no transcendentals)
__device__ __forceinline__ void kan_basis_b(float xv, float* Bv) {
    const float h = 0.4f;
#pragma unroll
    for (int j = 0; j < 16; j++) {
        float t0 = -2.0f + h * (float)(j - 3);
        float t1 = -2.0f + h * (float)(j - 2);
        Bv[j] = (xv >= t0 && xv < t1) ? 1.0f : 0.0f;
    }
#pragma unroll
    for (int d = 1; d <= 3; d++) {
        float inv = 1.0f / (h * (float)d);
#pragma unroll
        for (int j = 0; j < 16 - 3; j++) {
            if (j < 16 - d) {
                float tj   = -2.0f + h * (float)(j - 3);
                float tjd1 = -2.0f + h * (float)(j - 3 + d + 1);
                Bv[j] = (xv - tj) * inv * Bv[j] + (tjd1 - xv) * inv * Bv[j + 1];
            }
        }
        if (d < 3) {
            for (int j = 13; j < 16 - d; j++) {
                float tj   = -2.0f + h * (float)(j - 3);
                float tjd1 = -2.0f + h * (float)(j - 3 + d + 1);
                Bv[j] = (xv - tj) * inv * Bv[j] + (tjd1 - xv) * inv * Bv[j + 1];
            }
        }
    }
}

__device__ __forceinline__ void kan_basis(float xv, float& mishv, float* Bv) {
    mishv = mish_f(xv);
    kan_basis_b(xv, Bv);
}

__device__ __forceinline__ void split_hl(float v, __nv_bfloat16& hi, __nv_bfloat16& lo) {
    hi = __float2bfloat16(v);
    lo = __float2bfloat16(v - __bfloat162float(hi));
}

// ========== expand for layer 1: fused pool + basis + pad; 4 batch rows per block ==========
__global__ __launch_bounds__(256)
void expand49_kernel(const float* __restrict__ x, __nv_bfloat16* __restrict__ Ah,
                     __nv_bfloat16* __restrict__ Al) {
    __shared__ __nv_bfloat16 sh[4 * KP1];
    __shared__ __nv_bfloat16 sl[4 * KP1];
    int t = threadIdx.x;
    int b0 = blockIdx.x * 4;
    __nv_bfloat16 z = __float2bfloat16(0.f);

    if (t < 72) {
        int r = t / 18, c = 686 + (t - (t / 18) * 18);
        sh[r * KP1 + c] = z;
        sl[r * KP1 + c] = z;
    }

    if (t < 196) {
        int r = t / 49, i = t - r * 49;
        int b = b0 + r;
        int pr = i / 7, pc = i - pr * 7;
        const float* base = x + (size_t)b * 784 + pr * 4 * 28 + pc * 4;
        float s = 0.f;
#pragma unroll
        for (int k = 0; k < 4; k++) {
            float4 v = *(const float4*)(base + k * 28);
            s += v.x + v.y + v.z + v.w;
        }
        float xv = s * 0.0625f;
        float mishv, Bv[16];
        kan_basis(xv, mishv, Bv);
        __nv_bfloat16* rh = sh + r * KP1;
        __nv_bfloat16* rl = sl + r * KP1;
        split_hl(mishv, rh[i], rl[i]);
        int off = IN1 + i * NCOEF;
#pragma unroll
        for (int g = 0; g < NCOEF; g++) split_hl(Bv[g], rh[off + g], rl[off + g]);
    }
    __syncthreads();

    const uint4* s4h = (const uint4*)sh;
    const uint4* s4l = (const uint4*)sl;
    uint4* oh = (uint4*)(Ah + (size_t)b0 * KP1);
    uint4* ol = (uint4*)(Al + (size_t)b0 * KP1);
#pragma unroll
    for (int u = 0; u < 2; u++) {
        int w = u * 256 + t;
        if (w < 352) { oh[w] = s4h[w]; ol[w] = s4l[w]; }
    }
}

// ========== pack W^T (N rows, KP cols, K-major) as bf16 hi/lo ==========
__global__ void buildWt_kernel(const float* __restrict__ coef, const float* __restrict__ sb_,
                               const float* __restrict__ sp_, __nv_bfloat16* __restrict__ Wh,
                               __nv_bfloat16* __restrict__ Wl, int in, int out, int KP) {
    int idx = blockIdx.x * blockDim.x + threadIdx.x;
    if (idx >= out * KP) return;
    int n = idx / KP, k = idx - n * KP;
    float v = 0.f;
    if (k < in) {
        v = sb_[k * out + n];
    } else if (k < in * 14) {
        int q = k - in;
        int i = q / 13, g = q - i * 13;
        v = coef[((size_t)i * out + n) * 13 + g] * sp_[i * out + n];
    }
    __nv_bfloat16 hi, lo;
    split_hl(v, hi, lo);
    Wh[idx] = hi;
    Wl[idx] = lo;
}

// ========== pack layer-3 W (K rows, 10 cols) as fp32 ==========
__global__ void buildW3_kernel(const float* __restrict__ coef, const float* __restrict__ sb_,
                               const float* __restrict__ sp_, float* __restrict__ W) {
    int idx = blockIdx.x * blockDim.x + threadIdx.x;
    if (idx >= K2 * OUT3) return;
    int r = idx / OUT3, o = idx - r * OUT3;
    float v;
    if (r < HID) {
        v = sb_[r * OUT3 + o];
    } else {
        int q = r - HID;
        int i = q / 13, g = q - i * 13;
        v = coef[((size_t)i * OUT3 + o) * 13 + g] * sp_[i * OUT3 + o];
    }
    W[idx] = v;
}

// ================= GEMM common geometry =================
#define ASTRIDE     80                 // 64B data + 16B pad: conflict-free ldmatrix
#define AMAT_BYTES  (64 * ASTRIDE)     // 5120
#define BMAT_BYTES  (128 * ASTRIDE)    // 10240
#define STAGE_BYTES (2 * AMAT_BYTES + 2 * BMAT_BYTES)   // 30720
#define SMEM_GEMM   (3 * STAGE_BYTES + 512)

// ========== layer-1 GEMM (A from global) ==========
__global__ __launch_bounds__(256, 2)
void gemm_kernel(const __nv_bfloat16* __restrict__ Ah, const __nv_bfloat16* __restrict__ Al,
                 const __nv_bfloat16* __restrict__ Wh, const __nv_bfloat16* __restrict__ Wl,
                 const float* __restrict__ bias, float* __restrict__ C, int K, int Nc) {
    extern __shared__ char smem[];
    uint32_t sbase = smem_to_u32(smem);
    float* bsm = (float*)(smem + 3 * STAGE_BYTES);
    int tid = threadIdx.x, lane = tid & 31, wid = tid >> 5;
    int bm = blockIdx.y * 64, bn = blockIdx.x * 128;
    if (tid < 128) bsm[tid] = bias[bn + tid];

    const size_t strideA = (size_t)K * 2;
    const char* pAh = (const char*)Ah;
    const char* pAl = (const char*)Al;
    const char* pWh = (const char*)Wh;
    const char* pWl = (const char*)Wl;

    float acc[2][4][4];
#pragma unroll
    for (int i = 0; i < 2; i++)
#pragma unroll
        for (int j = 0; j < 4; j++)
#pragma unroll
            for (int q = 0; q < 4; q++) acc[i][j][q] = 0.f;

    int wm = (wid & 1) * 32, wn = (wid >> 1) * 32;
    int a_row = lane & 15, a_hi = lane >> 4;
    int bg = lane >> 3;
    int b_row = ((bg >> 1) << 3) + (lane & 7);
    int b_hi = bg & 1;

    int nch = K >> 5;
    int rowA = tid >> 2, chA = tid & 3;
    uint32_t soffA = rowA * ASTRIDE + chA * 16;

#define LOAD_CHUNK(stage, c) do { \
        size_t kb = (size_t)(c) * 64; \
        uint32_t sst = sbase + (stage) * STAGE_BYTES; \
        size_t ga = (size_t)(bm + rowA) * strideA + kb + chA * 16; \
        CP16(sst + soffA,              pAh + ga); \
        CP16(sst + AMAT_BYTES + soffA, pAl + ga); \
        _Pragma("unroll") \
        for (int u = 0; u < 2; u++) { \
            int idx = u * 256 + tid; \
            int row = idx >> 2, ch = idx & 3; \
            uint32_t soff = row * ASTRIDE + ch * 16; \
            size_t gb = (size_t)(bn + row) * strideA + kb + ch * 16; \
            CP16(sst + 2 * AMAT_BYTES + soff,              pWh + gb); \
            CP16(sst + 2 * AMAT_BYTES + BMAT_BYTES + soff, pWl + gb); \
        } \
    } while (0)

    LOAD_CHUNK(0, 0);
    CP_COMMIT();
    if (nch > 1) { LOAD_CHUNK(1, 1); CP_COMMIT(); }

    int st = 0;
    for (int c = 0; c < nch; c++) {
        if (c + 2 < nch) {
            int s2 = st + 2; if (s2 >= 3) s2 -= 3;
            LOAD_CHUNK(s2, c + 2);
            CP_COMMIT();
            CP_WAIT2();
        } else if (c + 1 < nch) {
            CP_WAIT1();
        } else {
            CP_WAIT0();
        }
        __syncthreads();

        uint32_t base = sbase + st * STAGE_BYTES;
        uint32_t aAh = base, aAl = base + AMAT_BYTES;
        uint32_t aBh = base + 2 * AMAT_BYTES, aBl = aBh + BMAT_BYTES;

#pragma unroll
        for (int kk = 0; kk < 2; kk++) {
            int kch = kk * 2;
            uint32_t ahf[2][4], alf[2][4], bhf[2][4], blf[2][4];
#pragma unroll
            for (int mt = 0; mt < 2; mt++) {
                uint32_t ao = (uint32_t)(wm + mt * 16 + a_row) * ASTRIDE + (kch + a_hi) * 16;
                LDSM4(ahf[mt], aAh + ao);
                LDSM4(alf[mt], aAl + ao);
            }
#pragma unroll
            for (int np = 0; np < 2; np++) {
                uint32_t bo = (uint32_t)(wn + np * 16 + b_row) * ASTRIDE + (kch + b_hi) * 16;
                LDSM4(bhf[np], aBh + bo);
                LDSM4(blf[np], aBl + bo);
            }
#pragma unroll
            for (int mt = 0; mt < 2; mt++)
#pragma unroll
                for (int nt = 0; nt < 4; nt++) {
                    int np = nt >> 1, s = (nt & 1) * 2;
                    MMA_BF16(acc[mt][nt], ahf[mt], bhf[np][s], bhf[np][s + 1]);
                    MMA_BF16(acc[mt][nt], ahf[mt], blf[np][s], blf[np][s + 1]);
                    MMA_BF16(acc[mt][nt], alf[mt], bhf[np][s], bhf[np][s + 1]);
                }
        }
        __syncthreads();
        if (++st == 3) st = 0;
    }
#undef LOAD_CHUNK

#pragma unroll
    for (int mt = 0; mt < 2; mt++) {
        int r0 = bm + wm + mt * 16 + (lane >> 2);
#pragma unroll
        for (int nt = 0; nt < 4; nt++) {
            int cl = wn + nt * 8 + (lane & 3) * 2;
            float bz0 = bsm[cl], bz1 = bsm[cl + 1];
            float2 v0, v1;
            v0.x = acc[mt][nt][0] + bz0;  v0.y = acc[mt][nt][1] + bz1;
            v1.x = acc[mt][nt][2] + bz0;  v1.y = acc[mt][nt][3] + bz1;
            *(float2*)(C + (size_t)r0 * Nc + bn + cl)       = v0;
            *(float2*)(C + (size_t)(r0 + 8) * Nc + bn + cl) = v1;
        }
    }
}

// ========== layer-2 GEMM with A computed inline from H (expand fused into producer) ==========
#define SMEM_H  (64 * HID * 4)                       // 65536
#define SMEM_G2 (3 * STAGE_BYTES + SMEM_H + 512)     // 158208

__global__ __launch_bounds__(256, 1)
void gemm2_fused_kernel(const float* __restrict__ H,
                        const __nv_bfloat16* __restrict__ Wh, const __nv_bfloat16* __restrict__ Wl,
                        const float* __restrict__ bias, float* __restrict__ C) {
    extern __shared__ char smem[];
    uint32_t sbase = smem_to_u32(smem);
    float* Hs  = (float*)(smem + 3 * STAGE_BYTES);
    float* bsm = (float*)(smem + 3 * STAGE_BYTES + SMEM_H);
    int tid = threadIdx.x, lane = tid & 31, wid = tid >> 5;
    int bm = blockIdx.y * 64, bn = blockIdx.x * 128;
    if (tid < 128) bsm[tid] = bias[bn + tid];

    // load H tile: rows [bm, bm+64) x 256 fp32 = 4096 float4, contiguous
    {
        const float4* Hg = (const float4*)(H + (size_t)bm * HID);
        float4* Hs4 = (float4*)Hs;
#pragma unroll
        for (int u = 0; u < 16; u++) Hs4[u * 256 + tid] = Hg[u * 256 + tid];
    }
    __syncthreads();

    const size_t strideB = (size_t)K2 * 2;
    const char* pWh = (const char*)Wh;
    const char* pWl = (const char*)Wl;

    float acc[2][4][4];
#pragma unroll
    for (int i = 0; i < 2; i++)
#pragma unroll
        for (int j = 0; j < 4; j++)
#pragma unroll
            for (int q = 0; q < 4; q++) acc[i][j][q] = 0.f;

    int wm = (wid & 1) * 32, wn = (wid >> 1) * 32;
    int a_row = lane & 15, a_hi = lane >> 4;
    int bg = lane >> 3;
    int b_row = ((bg >> 1) << 3) + (lane & 7);
    int b_hi = bg & 1;

    const int nch = K2 >> 5;   // 112
    int rowA = tid >> 2, cbA = tid & 3;          // A compute: row 0..63, 8-col block 0..3
    const float* Hrow = Hs + rowA * HID;

    // compute A chunk (32 bf16 cols starting at c*32) into stage; one STS.128 per matrix
#define GEN_A_CHUNK(stage, c) do { \
        char* sst = smem + (stage) * STAGE_BYTES; \
        int j0 = (c) * 32 + cbA * 8; \
        __nv_bfloat16 hi8[8], lo8[8]; \
        if (j0 < HID) { \
            _Pragma("unroll") \
            for (int e = 0; e < 8; e++) split_hl(mish_f(Hrow[j0 + e]), hi8[e], lo8[e]); \
        } else { \
            float Bv[16]; int cur_i = -1; \
            _Pragma("unroll") \
            for (int e = 0; e < 8; e++) { \
                int qq = j0 + e - HID; \
                int i = qq / 13, g = qq - i * 13; \
                if (i != cur_i) { kan_basis_b(Hrow[i], Bv); cur_i = i; } \
                split_hl(Bv[g], hi8[e], lo8[e]); \
            } \
        } \
        uint32_t off = (uint32_t)rowA * ASTRIDE + cbA * 16; \
        *(uint4*)(sst + off)              = *(uint4*)hi8; \
        *(uint4*)(sst + AMAT_BYTES + off) = *(uint4*)lo8; \
    } while (0)

#define LOAD_B_CHUNK(stage, c) do { \
        size_t kb = (size_t)(c) * 64; \
        uint32_t sst = sbase + (stage) * STAGE_BYTES; \
        _Pragma("unroll") \
        for (int u = 0; u < 2; u++) { \
            int idx = u * 256 + tid; \
            int row = idx >> 2, ch = idx & 3; \
            uint32_t soff = row * ASTRIDE + ch * 16; \
            size_t gb = (size_t)(bn + row) * strideB + kb + ch * 16; \
            CP16(sst + 2 * AMAT_BYTES + soff,              pWh + gb); \
            CP16(sst + 2 * AMAT_BYTES + BMAT_BYTES + soff, pWl + gb); \
        } \
    } while (0)

    LOAD_B_CHUNK(0, 0); CP_COMMIT(); GEN_A_CHUNK(0, 0);
    LOAD_B_CHUNK(1, 1); CP_COMMIT(); GEN_A_CHUNK(1, 1);

    int st = 0;
    for (int c = 0; c < nch; c++) {
        if (c + 2 < nch) {
            int s2 = st + 2; if (s2 >= 3) s2 -= 3;
            LOAD_B_CHUNK(s2, c + 2);
            CP_COMMIT();
            GEN_A_CHUNK(s2, c + 2);
            CP_WAIT2();
        } else if (c + 1 < nch) {
            CP_WAIT1();
        } else {
            CP_WAIT0();
        }
        __syncthreads();

        uint32_t base = sbase + st * STAGE_BYTES;
        uint32_t aAh = base, aAl = base + AMAT_BYTES;
        uint32_t aBh = base + 2 * AMAT_BYTES, aBl = aBh + BMAT_BYTES;

#pragma unroll
        for (int kk = 0; kk < 2; kk++) {
            int kch = kk * 2;
            uint32_t ahf[2][4], alf[2][4], bhf[2][4], blf[2][4];
#pragma unroll
            for (int mt = 0; mt < 2; mt++) {
                uint32_t ao = (uint32_t)(wm + mt * 16 + a_row) * ASTRIDE + (kch + a_hi) * 16;
                LDSM4(ahf[mt], aAh + ao);
                LDSM4(alf[mt], aAl + ao);
            }
#pragma unroll
            for (int np = 0; np < 2; np++) {
                uint32_t bo = (uint32_t)(wn + np * 16 + b_row) * ASTRIDE + (kch + b_hi) * 16;
                LDSM4(bhf[np], aBh + bo);
                LDSM4(blf[np], aBl + bo);
            }
#pragma unroll
            for (int mt = 0; mt < 2; mt++)
#pragma unroll
                for (int nt = 0; nt < 4; nt++) {
                    int np = nt >> 1, s = (nt & 1) * 2;
                    MMA_BF16(acc[mt][nt], ahf[mt], bhf[np][s], bhf[np][s + 1]);
                    MMA_BF16(acc[mt][nt], ahf[mt], blf[np][s], blf[np][s + 1]);
                    MMA_BF16(acc[mt][nt], alf[mt], bhf[np][s], bhf[np][s + 1]);
                }
        }
        __syncthreads();
        if (++st == 3) st = 0;
    }
#undef GEN_A_CHUNK
#undef LOAD_B_CHUNK

#pragma unroll
    for (int mt = 0; mt < 2; mt++) {
        int r0 = bm + wm + mt * 16 + (lane >> 2);
#pragma unroll
        for (int nt = 0; nt < 4; nt++) {
            int cl = wn + nt * 8 + (lane & 3) * 2;
            float bz0 = bsm[cl], bz1 = bsm[cl + 1];
            float2 v0, v1;
            v0.x = acc[mt][nt][0] + bz0;  v0.y = acc[mt][nt][1] + bz1;
            v1.x = acc[mt][nt][2] + bz0;  v1.y = acc[mt][nt][3] + bz1;
            *(float2*)(C + (size_t)r0 * HID + bn + cl)       = v0;
            *(float2*)(C + (size_t)(r0 + 8) * HID + bn + cl) = v1;
        }
    }
}

// ===== layer3 fused: H2(B,256) -> expand inline -> @W3(3584,10) + bias -> log_softmax =====
#define L3_ROWS 64
__global__ __launch_bounds__(256)
void layer3_fused_kernel(const float* __restrict__ H, const float* __restrict__ W3,
                         const float* __restrict__ bias, float* __restrict__ out) {
    __shared__ float Hs[L3_ROWS * 33];
    __shared__ float Wm[32 * 10];
    __shared__ float Wsp[32 * 13 * 10];
    __shared__ float bs[10];
    int t = threadIdx.x;
    int r0 = blockIdx.x * L3_ROWS;
    int rl = t >> 2, sub = t & 3;
    if (t < 10) bs[t] = bias[t];

    float acc[10];
#pragma unroll
    for (int o = 0; o < 10; o++) acc[o] = 0.f;

    for (int i0 = 0; i0 < HID; i0 += 32) {
        __syncthreads();
        for (int idx = t; idx < L3_ROWS * 32; idx += 256) {
            int row = idx >> 5, col = idx & 31;
            Hs[row * 33 + col] = H[(size_t)(r0 + row) * HID + i0 + col];
        }
        for (int idx = t; idx < 320; idx += 256)
            Wm[idx] = W3[(size_t)i0 * 10 + idx];
        for (int idx = t; idx < 4160; idx += 256)
            Wsp[idx] = W3[(size_t)(HID + i0 * 13) * 10 + idx];
        __syncthreads();

        for (int ii = sub; ii < 32; ii += 4) {
            float xv = Hs[rl * 33 + ii];
            float mishv, Bv[16];
            kan_basis(xv, mishv, Bv);
            const float* wm  = &Wm[ii * 10];
            const float* wsp = &Wsp[ii * 130];
#pragma unroll
            for (int o = 0; o < 10; o++) acc[o] = fmaf(mishv, wm[o], acc[o]);
#pragma unroll
            for (int g = 0; g < NCOEF; g++) {
                float bgv = Bv[g];
#pragma unroll
                for (int o = 0; o < 10; o++) acc[o] = fmaf(bgv, wsp[g * 10 + o], acc[o]);
            }
        }
    }

#pragma unroll
    for (int o = 0; o < 10; o++) {
        acc[o] += __shfl_xor_sync(0xFFFFFFFF, acc[o], 1);
        acc[o] += __shfl_xor_sync(0xFFFFFFFF, acc[o], 2);
    }
    if (sub == 0) {
#pragma unroll
        for (int o = 0; o < 10; o++) acc[o] += bs[o];
        float m = acc[0];
#pragma unroll
        for (int o = 1; o < 10; o++) m = fmaxf(m, acc[o]);
        float s = 0.f;
#pragma unroll
        for (int o = 0; o < 10; o++) s += expf(acc[o] - m);
        float ls = logf(s) + m;
        int row = r0 + rl;
#pragma unroll
        for (int o = 0; o < 10; o++) out[(size_t)row * 10 + o] = acc[o] - ls;
    }
}

// ================= host =================
extern "C" void kernel_launch(void* const* d_in, const int* in_sizes, int n_in,
                              void* d_out, int out_size) {
    const float* x     = (const float*)d_in[0];
    const float* coef1 = (const float*)d_in[1];
    const float* sb1   = (const float*)d_in[2];
    const float* sp1   = (const float*)d_in[3];
    const float* b1    = (const float*)d_in[4];
    const float* coef2 = (const float*)d_in[5];
    const float* sb2   = (const float*)d_in[6];
    const float* sp2   = (const float*)d_in[7];
    const float* b2    = (const float*)d_in[8];
    const float* coef3 = (const float*)d_in[9];
    const float* sb3   = (const float*)d_in[10];
    const float* sp3   = (const float*)d_in[11];
    const float* b3    = (const float*)d_in[12];
    float* out = (float*)d_out;

    float *H, *H2, *W3;
    __nv_bfloat16 *Ah, *Al, *Wh1, *Wl1, *Wh2, *Wl2;
    cudaGetSymbolAddress((void**)&H,   g_H);
    cudaGetSymbolAddress((void**)&H2,  g_H2);
    cudaGetSymbolAddress((void**)&Ah,  g_Ah);
    cudaGetSymbolAddress((void**)&Al,  g_Al);
    cudaGetSymbolAddress((void**)&Wh1, g_Wh1);
    cudaGetSymbolAddress((void**)&Wl1, g_Wl1);
    cudaGetSymbolAddress((void**)&Wh2, g_Wh2);
    cudaGetSymbolAddress((void**)&Wl2, g_Wl2);
    cudaGetSymbolAddress((void**)&W3,  g_W3);

    cudaFuncSetAttribute(gemm_kernel, cudaFuncAttributeMaxDynamicSharedMemorySize, SMEM_GEMM);
    cudaFuncSetAttribute(gemm2_fused_kernel, cudaFuncAttributeMaxDynamicSharedMemorySize, SMEM_G2);

    dim3 g1(HID / 128, BATCH / 64);   // (2, 128)

    buildWt_kernel<<<(HID * KP1 + 255) / 256, 256>>>(coef1, sb1, sp1, Wh1, Wl1, IN1, HID, KP1); // 0
    buildWt_kernel<<<(HID * K2 + 255) / 256, 256>>>(coef2, sb2, sp2, Wh2, Wl2, HID, HID, K2);   // 1
    expand49_kernel<<<BATCH / 4, 256>>>(x, Ah, Al);                                              // 2
    gemm_kernel<<<g1, 256, SMEM_GEMM>>>(Ah, Al, Wh1, Wl1, b1, H, KP1, HID);                      // 3 (ncu)
    buildW3_kernel<<<(K2 * OUT3 + 255) / 256, 256>>>(coef3, sb3, sp3, W3);                       // 4
    gemm2_fused_kernel<<<g1, 256, SMEM_G2>>>(H, Wh2, Wl2, b2, H2);                               // 5
    layer3_fused_kernel<<<BATCH / L3_ROWS, 256>>>(H2, W3, b3, out);                              // 6
}

// round 13
// speedup vs baseline: 1.4266x; 1.4266x over previous
#include <cuda_runtime.h>
#include <cuda_bf16.h>
#include <cstdint>
#include <math.h>

#define BATCH 8192
#define IN1   49
#define HID   256
#define NCOEF 13
#define KP1   704      // 49*14 = 686, padded to 64-multiple
#define K2    3584     // 256*14
#define OUT3  10

// ================= helpers (baseline PTX only: sm_80-era features) =================
__device__ __forceinline__ uint32_t smem_to_u32(const void* p) {
    uint32_t a;
    asm("{ .reg .u64 t; cvta.to.shared.u64 t, %1; cvt.u32.u64 %0, t; }" : "=r"(a) : "l"(p));
    return a;
}

#define CP16(dst, src) \
    asm volatile("cp.async.cg.shared.global [%0], [%1], 16;" :: "r"(dst), "l"(src) : "memory")
#define CP_COMMIT() asm volatile("cp.async.commit_group;" ::: "memory")
#define CP_WAIT2()  asm volatile("cp.async.wait_group 2;" ::: "memory")
#define CP_WAIT1()  asm volatile("cp.async.wait_group 1;" ::: "memory")
#define CP_WAIT0()  asm volatile("cp.async.wait_group 0;" ::: "memory")

#define LDSM4(r, addr) \
    asm volatile("ldmatrix.sync.aligned.m8n8.x4.shared.b16 {%0,%1,%2,%3}, [%4];" \
        : "=r"((r)[0]), "=r"((r)[1]), "=r"((r)[2]), "=r"((r)[3]) : "r"(addr))

#define MMA_BF16(d, a, b0, b1) \
    asm volatile("mma.sync.aligned.m16n8k16.row.col.f32.bf16.bf16.f32 " \
        "{%0,%1,%2,%3},{%4,%5,%6,%7},{%8,%9},{%0,%1,%2,%3};" \
        : "+f"((d)[0]), "+f"((d)[1]), "+f"((d)[2]), "+f"((d)[3]) \
        : "r"((a)[0]), "r"((a)[1]), "r"((a)[2]), "r"((a)[3]), "r"(b0), "r"(b1))

// ================= scratch =================
__device__ float         g_H [BATCH * HID];
__device__ __nv_bfloat16 g_Ah1[(size_t)BATCH * KP1];   // layer-1 A
__device__ __nv_bfloat16 g_Al1[(size_t)BATCH * KP1];
__device__ __nv_bfloat16 g_Ah2[(size_t)BATCH * K2];    // layer-2 A (separate: overlap safety)
__device__ __nv_bfloat16 g_Al2[(size_t)BATCH * K2];
__device__ __nv_bfloat16 g_Wh1[HID * KP1];
__device__ __nv_bfloat16 g_Wl1[HID * KP1];
__device__ __nv_bfloat16 g_Wh2[HID * K2];
__device__ __nv_bfloat16 g_Wl2[HID * K2];
__device__ float         g_W3[K2 * OUT3];

// ================= shared KAN math =================
__device__ __forceinline__ void kan_basis(float xv, float& mishv, float* Bv) {
    float sp = fmaxf(xv, 0.f) + log1pf(expf(-fabsf(xv)));
    mishv = xv * tanhf(sp);
    const float h = 0.4f;
#pragma unroll
    for (int j = 0; j < 16; j++) {
        float t0 = -2.0f + h * (float)(j - 3);
        float t1 = -2.0f + h * (float)(j - 2);
        Bv[j] = (xv >= t0 && xv < t1) ? 1.0f : 0.0f;
    }
#pragma unroll
    for (int d = 1; d <= 3; d++) {
        float inv = 1.0f / (h * (float)d);
#pragma unroll
        for (int j = 0; j < 16 - 3; j++) {
            if (j < 16 - d) {
                float tj   = -2.0f + h * (float)(j - 3);
                float tjd1 = -2.0f + h * (float)(j - 3 + d + 1);
                Bv[j] = (xv - tj) * inv * Bv[j] + (tjd1 - xv) * inv * Bv[j + 1];
            }
        }
        if (d < 3) {
            for (int j = 13; j < 16 - d; j++) {
                float tj   = -2.0f + h * (float)(j - 3);
                float tjd1 = -2.0f + h * (float)(j - 3 + d + 1);
                Bv[j] = (xv - tj) * inv * Bv[j] + (tjd1 - xv) * inv * Bv[j + 1];
            }
        }
    }
}

__device__ __forceinline__ void split_hl(float v, __nv_bfloat16& hi, __nv_bfloat16& lo) {
    hi = __float2bfloat16(v);
    lo = __float2bfloat16(v - __bfloat162float(hi));
}

// ========== expand for in=256: 1 batch row per block (b0 = row offset) ==========
__global__ __launch_bounds__(256)
void expand256_kernel(const float* __restrict__ H, __nv_bfloat16* __restrict__ Ah,
                      __nv_bfloat16* __restrict__ Al, int b0) {
    __shared__ __nv_bfloat16 sh[K2];
    __shared__ __nv_bfloat16 sl[K2];
    int b = blockIdx.x + b0, i = threadIdx.x;
    float xv = H[b * HID + i];
    float mishv, Bv[16];
    kan_basis(xv, mishv, Bv);
    split_hl(mishv, sh[i], sl[i]);
    int off = HID + i * NCOEF;
#pragma unroll
    for (int g = 0; g < NCOEF; g++) split_hl(Bv[g], sh[off + g], sl[off + g]);
    __syncthreads();

    const uint4* s4h = (const uint4*)sh;
    const uint4* s4l = (const uint4*)sl;
    uint4* oh = (uint4*)(Ah + (size_t)b * K2);
    uint4* ol = (uint4*)(Al + (size_t)b * K2);
#pragma unroll
    for (int u = 0; u < 2; u++) {
        int t = u * 256 + i;
        if (t < 448) { oh[t] = s4h[t]; ol[t] = s4l[t]; }
    }
}

// ========== expand for layer 1: fused pool + basis + pad; 4 batch rows per block ==========
__global__ __launch_bounds__(256)
void expand49_kernel(const float* __restrict__ x, __nv_bfloat16* __restrict__ Ah,
                     __nv_bfloat16* __restrict__ Al) {
    __shared__ __nv_bfloat16 sh[4 * KP1];
    __shared__ __nv_bfloat16 sl[4 * KP1];
    int t = threadIdx.x;
    int b0 = blockIdx.x * 4;
    __nv_bfloat16 z = __float2bfloat16(0.f);

    if (t < 72) {
        int r = t / 18, c = 686 + (t - (t / 18) * 18);
        sh[r * KP1 + c] = z;
        sl[r * KP1 + c] = z;
    }

    if (t < 196) {
        int r = t / 49, i = t - r * 49;
        int b = b0 + r;
        int pr = i / 7, pc = i - pr * 7;
        const float* base = x + (size_t)b * 784 + pr * 4 * 28 + pc * 4;
        float s = 0.f;
#pragma unroll
        for (int k = 0; k < 4; k++) {
            float4 v = *(const float4*)(base + k * 28);
            s += v.x + v.y + v.z + v.w;
        }
        float xv = s * 0.0625f;
        float mishv, Bv[16];
        kan_basis(xv, mishv, Bv);
        __nv_bfloat16* rh = sh + r * KP1;
        __nv_bfloat16* rl = sl + r * KP1;
        split_hl(mishv, rh[i], rl[i]);
        int off = IN1 + i * NCOEF;
#pragma unroll
        for (int g = 0; g < NCOEF; g++) split_hl(Bv[g], rh[off + g], rl[off + g]);
    }
    __syncthreads();

    const uint4* s4h = (const uint4*)sh;
    const uint4* s4l = (const uint4*)sl;
    uint4* oh = (uint4*)(Ah + (size_t)b0 * KP1);
    uint4* ol = (uint4*)(Al + (size_t)b0 * KP1);
#pragma unroll
    for (int u = 0; u < 2; u++) {
        int w = u * 256 + t;
        if (w < 352) { oh[w] = s4h[w]; ol[w] = s4l[w]; }
    }
}

// ========== pack W^T (N rows, KP cols, K-major) as bf16 hi/lo ==========
__global__ void buildWt_kernel(const float* __restrict__ coef, const float* __restrict__ sb_,
                               const float* __restrict__ sp_, __nv_bfloat16* __restrict__ Wh,
                               __nv_bfloat16* __restrict__ Wl, int in, int out, int KP) {
    int idx = blockIdx.x * blockDim.x + threadIdx.x;
    if (idx >= out * KP) return;
    int n = idx / KP, k = idx - n * KP;
    float v = 0.f;
    if (k < in) {
        v = sb_[k * out + n];
    } else if (k < in * 14) {
        int q = k - in;
        int i = q / 13, g = q - i * 13;
        v = coef[((size_t)i * out + n) * 13 + g] * sp_[i * out + n];
    }
    __nv_bfloat16 hi, lo;
    split_hl(v, hi, lo);
    Wh[idx] = hi;
    Wl[idx] = lo;
}

// ========== pack layer-3 W (K rows, 10 cols) as fp32 ==========
__global__ void buildW3_kernel(const float* __restrict__ coef, const float* __restrict__ sb_,
                               const float* __restrict__ sp_, float* __restrict__ W) {
    int idx = blockIdx.x * blockDim.x + threadIdx.x;
    if (idx >= K2 * OUT3) return;
    int r = idx / OUT3, o = idx - r * OUT3;
    float v;
    if (r < HID) {
        v = sb_[r * OUT3 + o];
    } else {
        int q = r - HID;
        int i = q / 13, g = q - i * 13;
        v = coef[((size_t)i * OUT3 + o) * 13 + g] * sp_[i * OUT3 + o];
    }
    W[idx] = v;
}

// ================= HMMA GEMM (round-9 proven core + m0 row offset) =================
#define ASTRIDE     80
#define AMAT_BYTES  (64 * ASTRIDE)     // 5120
#define BMAT_BYTES  (128 * ASTRIDE)    // 10240
#define STAGE_BYTES (2 * AMAT_BYTES + 2 * BMAT_BYTES)   // 30720
#define SMEM_GEMM   (3 * STAGE_BYTES + 512)

__global__ __launch_bounds__(256, 2)
void gemm_kernel(const __nv_bfloat16* __restrict__ Ah, const __nv_bfloat16* __restrict__ Al,
                 const __nv_bfloat16* __restrict__ Wh, const __nv_bfloat16* __restrict__ Wl,
                 const float* __restrict__ bias, float* __restrict__ C, int K, int Nc, int m0) {
    extern __shared__ char smem[];
    uint32_t sbase = smem_to_u32(smem);
    float* bsm = (float*)(smem + 3 * STAGE_BYTES);
    int tid = threadIdx.x, lane = tid & 31, wid = tid >> 5;
    int bm = blockIdx.y * 64 + m0, bn = blockIdx.x * 128;
    if (tid < 128) bsm[tid] = bias[bn + tid];

    const size_t strideA = (size_t)K * 2;
    const char* pAh = (const char*)Ah;
    const char* pAl = (const char*)Al;
    const char* pWh = (const char*)Wh;
    const char* pWl = (const char*)Wl;

    float acc[2][4][4];
#pragma unroll
    for (int i = 0; i < 2; i++)
#pragma unroll
        for (int j = 0; j < 4; j++)
#pragma unroll
            for (int q = 0; q < 4; q++) acc[i][j][q] = 0.f;

    int wm = (wid & 1) * 32, wn = (wid >> 1) * 32;
    int a_row = lane & 15, a_hi = lane >> 4;
    int bg = lane >> 3;
    int b_row = ((bg >> 1) << 3) + (lane & 7);
    int b_hi = bg & 1;

    int nch = K >> 5;
    int rowA = tid >> 2, chA = tid & 3;
    uint32_t soffA = rowA * ASTRIDE + chA * 16;

#define LOAD_CHUNK(stage, c) do { \
        size_t kb = (size_t)(c) * 64; \
        uint32_t sst = sbase + (stage) * STAGE_BYTES; \
        size_t ga = (size_t)(bm + rowA) * strideA + kb + chA * 16; \
        CP16(sst + soffA,              pAh + ga); \
        CP16(sst + AMAT_BYTES + soffA, pAl + ga); \
        _Pragma("unroll") \
        for (int u = 0; u < 2; u++) { \
            int idx = u * 256 + tid; \
            int row = idx >> 2, ch = idx & 3; \
            uint32_t soff = row * ASTRIDE + ch * 16; \
            size_t gb = (size_t)(bn + row) * strideA + kb + ch * 16; \
            CP16(sst + 2 * AMAT_BYTES + soff,              pWh + gb); \
            CP16(sst + 2 * AMAT_BYTES + BMAT_BYTES + soff, pWl + gb); \
        } \
    } while (0)

    LOAD_CHUNK(0, 0);
    CP_COMMIT();
    if (nch > 1) { LOAD_CHUNK(1, 1); CP_COMMIT(); }

    int st = 0;
    for (int c = 0; c < nch; c++) {
        if (c + 2 < nch) {
            int s2 = st + 2; if (s2 >= 3) s2 -= 3;
            LOAD_CHUNK(s2, c + 2);
            CP_COMMIT();
            CP_WAIT2();
        } else if (c + 1 < nch) {
            CP_WAIT1();
        } else {
            CP_WAIT0();
        }
        __syncthreads();

        uint32_t base = sbase + st * STAGE_BYTES;
        uint32_t aAh = base, aAl = base + AMAT_BYTES;
        uint32_t aBh = base + 2 * AMAT_BYTES, aBl = aBh + BMAT_BYTES;

#pragma unroll
        for (int kk = 0; kk < 2; kk++) {
            int kch = kk * 2;
            uint32_t ahf[2][4], alf[2][4], bhf[2][4], blf[2][4];
#pragma unroll
            for (int mt = 0; mt < 2; mt++) {
                uint32_t ao = (uint32_t)(wm + mt * 16 + a_row) * ASTRIDE + (kch + a_hi) * 16;
                LDSM4(ahf[mt], aAh + ao);
                LDSM4(alf[mt], aAl + ao);
            }
#pragma unroll
            for (int np = 0; np < 2; np++) {
                uint32_t bo = (uint32_t)(wn + np * 16 + b_row) * ASTRIDE + (kch + b_hi) * 16;
                LDSM4(bhf[np], aBh + bo);
                LDSM4(blf[np], aBl + bo);
            }
#pragma unroll
            for (int mt = 0; mt < 2; mt++)
#pragma unroll
                for (int nt = 0; nt < 4; nt++) {
                    int np = nt >> 1, s = (nt & 1) * 2;
                    MMA_BF16(acc[mt][nt], ahf[mt], bhf[np][s], bhf[np][s + 1]);
                    MMA_BF16(acc[mt][nt], ahf[mt], blf[np][s], blf[np][s + 1]);
                    MMA_BF16(acc[mt][nt], alf[mt], bhf[np][s], bhf[np][s + 1]);
                }
        }
        __syncthreads();
        if (++st == 3) st = 0;
    }
#undef LOAD_CHUNK

#pragma unroll
    for (int mt = 0; mt < 2; mt++) {
        int r0 = bm + wm + mt * 16 + (lane >> 2);
#pragma unroll
        for (int nt = 0; nt < 4; nt++) {
            int cl = wn + nt * 8 + (lane & 3) * 2;
            float bz0 = bsm[cl], bz1 = bsm[cl + 1];
            float2 v0, v1;
            v0.x = acc[mt][nt][0] + bz0;  v0.y = acc[mt][nt][1] + bz1;
            v1.x = acc[mt][nt][2] + bz0;  v1.y = acc[mt][nt][3] + bz1;
            *(float2*)(C + (size_t)r0 * Nc + bn + cl)       = v0;
            *(float2*)(C + (size_t)(r0 + 8) * Nc + bn + cl) = v1;
        }
    }
}

// ===== layer3 fused: H(B,256) -> expand inline -> @W3(3584,10) + bias -> log_softmax =====
#define L3_ROWS 64
__global__ __launch_bounds__(256)
void layer3_fused_kernel(const float* __restrict__ H, const float* __restrict__ W3,
                         const float* __restrict__ bias, float* __restrict__ out) {
    __shared__ float Hs[L3_ROWS * 33];
    __shared__ float Wm[32 * 10];
    __shared__ float Wsp[32 * 13 * 10];
    __shared__ float bs[10];
    int t = threadIdx.x;
    int r0 = blockIdx.x * L3_ROWS;
    int rl = t >> 2, sub = t & 3;
    if (t < 10) bs[t] = bias[t];

    float acc[10];
#pragma unroll
    for (int o = 0; o < 10; o++) acc[o] = 0.f;

    for (int i0 = 0; i0 < HID; i0 += 32) {
        __syncthreads();
        for (int idx = t; idx < L3_ROWS * 32; idx += 256) {
            int row = idx >> 5, col = idx & 31;
            Hs[row * 33 + col] = H[(size_t)(r0 + row) * HID + i0 + col];
        }
        for (int idx = t; idx < 320; idx += 256)
            Wm[idx] = W3[(size_t)i0 * 10 + idx];
        for (int idx = t; idx < 4160; idx += 256)
            Wsp[idx] = W3[(size_t)(HID + i0 * 13) * 10 + idx];
        __syncthreads();

        for (int ii = sub; ii < 32; ii += 4) {
            float xv = Hs[rl * 33 + ii];
            float mishv, Bv[16];
            kan_basis(xv, mishv, Bv);
            const float* wm  = &Wm[ii * 10];
            const float* wsp = &Wsp[ii * 130];
#pragma unroll
            for (int o = 0; o < 10; o++) acc[o] = fmaf(mishv, wm[o], acc[o]);
#pragma unroll
            for (int g = 0; g < NCOEF; g++) {
                float bgv = Bv[g];
#pragma unroll
                for (int o = 0; o < 10; o++) acc[o] = fmaf(bgv, wsp[g * 10 + o], acc[o]);
            }
        }
    }

#pragma unroll
    for (int o = 0; o < 10; o++) {
        acc[o] += __shfl_xor_sync(0xFFFFFFFF, acc[o], 1);
        acc[o] += __shfl_xor_sync(0xFFFFFFFF, acc[o], 2);
    }
    if (sub == 0) {
#pragma unroll
        for (int o = 0; o < 10; o++) acc[o] += bs[o];
        float m = acc[0];
#pragma unroll
        for (int o = 1; o < 10; o++) m = fmaxf(m, acc[o]);
        float s = 0.f;
#pragma unroll
        for (int o = 0; o < 10; o++) s += expf(acc[o] - m);
        float ls = logf(s) + m;
        int row = r0 + rl;
#pragma unroll
        for (int o = 0; o < 10; o++) out[(size_t)row * 10 + o] = acc[o] - ls;
    }
}

// ================= host =================
extern "C" void kernel_launch(void* const* d_in, const int* in_sizes, int n_in,
                              void* d_out, int out_size) {
    const float* x     = (const float*)d_in[0];
    const float* coef1 = (const float*)d_in[1];
    const float* sb1   = (const float*)d_in[2];
    const float* sp1   = (const float*)d_in[3];
    const float* b1    = (const float*)d_in[4];
    const float* coef2 = (const float*)d_in[5];
    const float* sb2   = (const float*)d_in[6];
    const float* sp2   = (const float*)d_in[7];
    const float* b2    = (const float*)d_in[8];
    const float* coef3 = (const float*)d_in[9];
    const float* sb3   = (const float*)d_in[10];
    const float* sp3   = (const float*)d_in[11];
    const float* b3    = (const float*)d_in[12];
    float* out = (float*)d_out;

    float *H, *W3;
    __nv_bfloat16 *Ah1, *Al1, *Ah2, *Al2, *Wh1, *Wl1, *Wh2, *Wl2;
    cudaGetSymbolAddress((void**)&H,   g_H);
    cudaGetSymbolAddress((void**)&Ah1, g_Ah1);
    cudaGetSymbolAddress((void**)&Al1, g_Al1);
    cudaGetSymbolAddress((void**)&Ah2, g_Ah2);
    cudaGetSymbolAddress((void**)&Al2, g_Al2);
    cudaGetSymbolAddress((void**)&Wh1, g_Wh1);
    cudaGetSymbolAddress((void**)&Wl1, g_Wl1);
    cudaGetSymbolAddress((void**)&Wh2, g_Wh2);
    cudaGetSymbolAddress((void**)&Wl2, g_Wl2);
    cudaGetSymbolAddress((void**)&W3,  g_W3);

    cudaFuncSetAttribute(gemm_kernel, cudaFuncAttributeMaxDynamicSharedMemorySize, SMEM_GEMM);

    // one-time stream/event setup (host resources only; no device memory)
    static cudaStream_t sA = nullptr, sB = nullptr;
    static cudaEvent_t ev0 = nullptr, evW1 = nullptr, evW2 = nullptr,
                       e1a = nullptr, e1b = nullptr, eExa = nullptr, eExb = nullptr;
    if (!sA) {
        cudaStreamCreateWithFlags(&sA, cudaStreamNonBlocking);
        cudaStreamCreateWithFlags(&sB, cudaStreamNonBlocking);
        cudaEventCreateWithFlags(&ev0,  cudaEventDisableTiming);
        cudaEventCreateWithFlags(&evW1, cudaEventDisableTiming);
        cudaEventCreateWithFlags(&evW2, cudaEventDisableTiming);
        cudaEventCreateWithFlags(&e1a,  cudaEventDisableTiming);
        cudaEventCreateWithFlags(&e1b,  cudaEventDisableTiming);
        cudaEventCreateWithFlags(&eExa, cudaEventDisableTiming);
        cudaEventCreateWithFlags(&eExb, cudaEventDisableTiming);
    }

    const int MH = BATCH / 2;          // 4096
    dim3 gh(HID / 128, MH / 64);       // (2, 64) per M-half

    // ---- fork prologue onto side streams ----
    cudaEventRecord(ev0, 0);
    cudaStreamWaitEvent(sA, ev0, 0);
    buildWt_kernel<<<(HID * KP1 + 255) / 256, 256, 0, sA>>>(coef1, sb1, sp1, Wh1, Wl1, IN1, HID, KP1);
    cudaEventRecord(evW1, sA);
    cudaStreamWaitEvent(sB, ev0, 0);
    buildWt_kernel<<<(HID * K2 + 255) / 256, 256, 0, sB>>>(coef2, sb2, sp2, Wh2, Wl2, HID, HID, K2);
    buildW3_kernel<<<(K2 * OUT3 + 255) / 256, 256, 0, sB>>>(coef3, sb3, sp3, W3);
    cudaEventRecord(evW2, sB);

    // ---- main chain on default stream, M-split pipelined with sA ----
    expand49_kernel<<<BATCH / 4, 256>>>(x, Ah1, Al1);
    cudaStreamWaitEvent(0, evW1, 0);
    gemm_kernel<<<gh, 256, SMEM_GEMM>>>(Ah1, Al1, Wh1, Wl1, b1, H, KP1, HID, 0);   // gemm1_a
    cudaEventRecord(e1a, 0);
    gemm_kernel<<<gh, 256, SMEM_GEMM>>>(Ah1, Al1, Wh1, Wl1, b1, H, KP1, HID, MH);  // gemm1_b
    cudaEventRecord(e1b, 0);

    // expand halves on sA, each gated on its gemm1 half (writes Ah2/Al2: no overlap with gemm1 reads of Ah1/Al1)
    cudaStreamWaitEvent(sA, e1a, 0);
    expand256_kernel<<<MH, 256, 0, sA>>>(H, Ah2, Al2, 0);                           // expand_a
    cudaEventRecord(eExa, sA);
    cudaStreamWaitEvent(sA, e1b, 0);
    expand256_kernel<<<MH, 256, 0, sA>>>(H, Ah2, Al2, MH);                          // expand_b
    cudaEventRecord(eExb, sA);

    // gemm2 halves on default stream (in-place H writes; row-disjoint from expand_b reads)
    cudaStreamWaitEvent(0, eExa, 0);
    cudaStreamWaitEvent(0, evW2, 0);
    gemm_kernel<<<gh, 256, SMEM_GEMM>>>(Ah2, Al2, Wh2, Wl2, b2, H, K2, HID, 0);    // gemm2_a
    cudaStreamWaitEvent(0, eExb, 0);
    gemm_kernel<<<gh, 256, SMEM_GEMM>>>(Ah2, Al2, Wh2, Wl2, b2, H, K2, HID, MH);   // gemm2_b

    layer3_fused_kernel<<<BATCH / L3_ROWS, 256>>>(H, W3, b3, out);
}

// round 14
// speedup vs baseline: 1.8339x; 1.2855x over previous
#include <cuda_runtime.h>
#include <cuda_bf16.h>
#include <cstdint>
#include <math.h>

#define BATCH 8192
#define IN1   49
#define HID   256
#define NCOEF 13
#define KP1   704      // 49*14 = 686, padded to 64-multiple
#define K2    3584     // 256*14
#define OUT3  10

// ================= helpers (baseline PTX only: sm_80-era features) =================
__device__ __forceinline__ uint32_t smem_to_u32(const void* p) {
    uint32_t a;
    asm("{ .reg .u64 t; cvta.to.shared.u64 t, %1; cvt.u32.u64 %0, t; }" : "=r"(a) : "l"(p));
    return a;
}

#define CP16(dst, src) \
    asm volatile("cp.async.cg.shared.global [%0], [%1], 16;" :: "r"(dst), "l"(src) : "memory")
#define CP_COMMIT() asm volatile("cp.async.commit_group;" ::: "memory")
#define CP_WAIT2()  asm volatile("cp.async.wait_group 2;" ::: "memory")
#define CP_WAIT1()  asm volatile("cp.async.wait_group 1;" ::: "memory")
#define CP_WAIT0()  asm volatile("cp.async.wait_group 0;" ::: "memory")

#define LDSM4(r, addr) \
    asm volatile("ldmatrix.sync.aligned.m8n8.x4.shared.b16 {%0,%1,%2,%3}, [%4];" \
        : "=r"((r)[0]), "=r"((r)[1]), "=r"((r)[2]), "=r"((r)[3]) : "r"(addr))

#define MMA_BF16(d, a, b0, b1) \
    asm volatile("mma.sync.aligned.m16n8k16.row.col.f32.bf16.bf16.f32 " \
        "{%0,%1,%2,%3},{%4,%5,%6,%7},{%8,%9},{%0,%1,%2,%3};" \
        : "+f"((d)[0]), "+f"((d)[1]), "+f"((d)[2]), "+f"((d)[3]) \
        : "r"((a)[0]), "r"((a)[1]), "r"((a)[2]), "r"((a)[3]), "r"(b0), "r"(b1))

// ================= scratch =================
__device__ float         g_H [BATCH * HID];
__device__ __nv_bfloat16 g_Ah[(size_t)BATCH * K2];
__device__ __nv_bfloat16 g_Al[(size_t)BATCH * K2];
__device__ __nv_bfloat16 g_Wh1[HID * KP1];
__device__ __nv_bfloat16 g_Wl1[HID * KP1];
__device__ __nv_bfloat16 g_Wh2[HID * K2];
__device__ __nv_bfloat16 g_Wl2[HID * K2];
__device__ float         g_W3[K2 * OUT3];

// ================= shared KAN math =================
__device__ __forceinline__ void kan_basis(float xv, float& mishv, float* Bv) {
    float sp = fmaxf(xv, 0.f) + log1pf(expf(-fabsf(xv)));
    mishv = xv * tanhf(sp);
    const float h = 0.4f;
#pragma unroll
    for (int j = 0; j < 16; j++) {
        float t0 = -2.0f + h * (float)(j - 3);
        float t1 = -2.0f + h * (float)(j - 2);
        Bv[j] = (xv >= t0 && xv < t1) ? 1.0f : 0.0f;
    }
#pragma unroll
    for (int d = 1; d <= 3; d++) {
        float inv = 1.0f / (h * (float)d);
#pragma unroll
        for (int j = 0; j < 16 - 3; j++) {
            if (j < 16 - d) {
                float tj   = -2.0f + h * (float)(j - 3);
                float tjd1 = -2.0f + h * (float)(j - 3 + d + 1);
                Bv[j] = (xv - tj) * inv * Bv[j] + (tjd1 - xv) * inv * Bv[j + 1];
            }
        }
        if (d < 3) {
            for (int j = 13; j < 16 - d; j++) {
                float tj   = -2.0f + h * (float)(j - 3);
                float tjd1 = -2.0f + h * (float)(j - 3 + d + 1);
                Bv[j] = (xv - tj) * inv * Bv[j] + (tjd1 - xv) * inv * Bv[j + 1];
            }
        }
    }
}

__device__ __forceinline__ void split_hl(float v, __nv_bfloat16& hi, __nv_bfloat16& lo) {
    hi = __float2bfloat16(v);
    lo = __float2bfloat16(v - __bfloat162float(hi));
}

// ========== expand for in=256 (layer 2 input): 1 batch row per block ==========
__global__ __launch_bounds__(256)
void expand256_kernel(const float* __restrict__ H, __nv_bfloat16* __restrict__ Ah,
                      __nv_bfloat16* __restrict__ Al) {
    __shared__ __nv_bfloat16 sh[K2];
    __shared__ __nv_bfloat16 sl[K2];
    int b = blockIdx.x, i = threadIdx.x;
    float xv = H[b * HID + i];
    float mishv, Bv[16];
    kan_basis(xv, mishv, Bv);
    split_hl(mishv, sh[i], sl[i]);
    int off = HID + i * NCOEF;
#pragma unroll
    for (int g = 0; g < NCOEF; g++) split_hl(Bv[g], sh[off + g], sl[off + g]);
    __syncthreads();

    const uint4* s4h = (const uint4*)sh;
    const uint4* s4l = (const uint4*)sl;
    uint4* oh = (uint4*)(Ah + (size_t)b * K2);
    uint4* ol = (uint4*)(Al + (size_t)b * K2);
#pragma unroll
    for (int u = 0; u < 2; u++) {
        int t = u * 256 + i;
        if (t < 448) { oh[t] = s4h[t]; ol[t] = s4l[t]; }
    }
}

// ========== expand for layer 1: fused pool + basis + pad; 4 batch rows per block ==========
__global__ __launch_bounds__(256)
void expand49_kernel(const float* __restrict__ x, __nv_bfloat16* __restrict__ Ah,
                     __nv_bfloat16* __restrict__ Al) {
    __shared__ __nv_bfloat16 sh[4 * KP1];
    __shared__ __nv_bfloat16 sl[4 * KP1];
    int t = threadIdx.x;
    int b0 = blockIdx.x * 4;
    __nv_bfloat16 z = __float2bfloat16(0.f);

    if (t < 72) {
        int r = t / 18, c = 686 + (t - (t / 18) * 18);
        sh[r * KP1 + c] = z;
        sl[r * KP1 + c] = z;
    }

    if (t < 196) {
        int r = t / 49, i = t - r * 49;
        int b = b0 + r;
        int pr = i / 7, pc = i - pr * 7;
        const float* base = x + (size_t)b * 784 + pr * 4 * 28 + pc * 4;
        float s = 0.f;
#pragma unroll
        for (int k = 0; k < 4; k++) {
            float4 v = *(const float4*)(base + k * 28);
            s += v.x + v.y + v.z + v.w;
        }
        float xv = s * 0.0625f;
        float mishv, Bv[16];
        kan_basis(xv, mishv, Bv);
        __nv_bfloat16* rh = sh + r * KP1;
        __nv_bfloat16* rl = sl + r * KP1;
        split_hl(mishv, rh[i], rl[i]);
        int off = IN1 + i * NCOEF;
#pragma unroll
        for (int g = 0; g < NCOEF; g++) split_hl(Bv[g], rh[off + g], rl[off + g]);
    }
    __syncthreads();

    const uint4* s4h = (const uint4*)sh;
    const uint4* s4l = (const uint4*)sl;
    uint4* oh = (uint4*)(Ah + (size_t)b0 * KP1);
    uint4* ol = (uint4*)(Al + (size_t)b0 * KP1);
#pragma unroll
    for (int u = 0; u < 2; u++) {
        int w = u * 256 + t;
        if (w < 352) { oh[w] = s4h[w]; ol[w] = s4l[w]; }
    }
}

// ========== pack W^T (N rows, KP cols, K-major) as bf16 hi/lo ==========
__global__ void buildWt_kernel(const float* __restrict__ coef, const float* __restrict__ sb_,
                               const float* __restrict__ sp_, __nv_bfloat16* __restrict__ Wh,
                               __nv_bfloat16* __restrict__ Wl, int in, int out, int KP) {
    int idx = blockIdx.x * blockDim.x + threadIdx.x;
    if (idx >= out * KP) return;
    int n = idx / KP, k = idx - n * KP;
    float v = 0.f;
    if (k < in) {
        v = sb_[k * out + n];
    } else if (k < in * 14) {
        int q = k - in;
        int i = q / 13, g = q - i * 13;
        v = coef[((size_t)i * out + n) * 13 + g] * sp_[i * out + n];
    }
    __nv_bfloat16 hi, lo;
    split_hl(v, hi, lo);
    Wh[idx] = hi;
    Wl[idx] = lo;
}

// ========== pack layer-3 W (K rows, 10 cols) as fp32 ==========
__global__ void buildW3_kernel(const float* __restrict__ coef, const float* __restrict__ sb_,
                               const float* __restrict__ sp_, float* __restrict__ W) {
    int idx = blockIdx.x * blockDim.x + threadIdx.x;
    if (idx >= K2 * OUT3) return;
    int r = idx / OUT3, o = idx - r * OUT3;
    float v;
    if (r < HID) {
        v = sb_[r * OUT3 + o];
    } else {
        int q = r - HID;
        int i = q / 13, g = q - i * 13;
        v = coef[((size_t)i * OUT3 + o) * 13 + g] * sp_[i * OUT3 + o];
    }
    W[idx] = v;
}

// ================= HMMA GEMM (round-9 proven core) =================
#define ASTRIDE     80
#define AMAT_BYTES  (64 * ASTRIDE)     // 5120
#define BMAT_BYTES  (128 * ASTRIDE)    // 10240
#define STAGE_BYTES (2 * AMAT_BYTES + 2 * BMAT_BYTES)   // 30720
#define SMEM_GEMM   (3 * STAGE_BYTES + 512)

__global__ __launch_bounds__(256, 2)
void gemm_kernel(const __nv_bfloat16* __restrict__ Ah, const __nv_bfloat16* __restrict__ Al,
                 const __nv_bfloat16* __restrict__ Wh, const __nv_bfloat16* __restrict__ Wl,
                 const float* __restrict__ bias, float* __restrict__ C, int K, int Nc) {
    extern __shared__ char smem[];
    uint32_t sbase = smem_to_u32(smem);
    float* bsm = (float*)(smem + 3 * STAGE_BYTES);
    int tid = threadIdx.x, lane = tid & 31, wid = tid >> 5;
    int bm = blockIdx.y * 64, bn = blockIdx.x * 128;
    if (tid < 128) bsm[tid] = bias[bn + tid];

    const size_t strideA = (size_t)K * 2;
    const char* pAh = (const char*)Ah;
    const char* pAl = (const char*)Al;
    const char* pWh = (const char*)Wh;
    const char* pWl = (const char*)Wl;

    float acc[2][4][4];
#pragma unroll
    for (int i = 0; i < 2; i++)
#pragma unroll
        for (int j = 0; j < 4; j++)
#pragma unroll
            for (int q = 0; q < 4; q++) acc[i][j][q] = 0.f;

    int wm = (wid & 1) * 32, wn = (wid >> 1) * 32;
    int a_row = lane & 15, a_hi = lane >> 4;
    int bg = lane >> 3;
    int b_row = ((bg >> 1) << 3) + (lane & 7);
    int b_hi = bg & 1;

    int nch = K >> 5;
    int rowA = tid >> 2, chA = tid & 3;
    uint32_t soffA = rowA * ASTRIDE + chA * 16;

#define LOAD_CHUNK(stage, c) do { \
        size_t kb = (size_t)(c) * 64; \
        uint32_t sst = sbase + (stage) * STAGE_BYTES; \
        size_t ga = (size_t)(bm + rowA) * strideA + kb + chA * 16; \
        CP16(sst + soffA,              pAh + ga); \
        CP16(sst + AMAT_BYTES + soffA, pAl + ga); \
        _Pragma("unroll") \
        for (int u = 0; u < 2; u++) { \
            int idx = u * 256 + tid; \
            int row = idx >> 2, ch = idx & 3; \
            uint32_t soff = row * ASTRIDE + ch * 16; \
            size_t gb = (size_t)(bn + row) * strideA + kb + ch * 16; \
            CP16(sst + 2 * AMAT_BYTES + soff,              pWh + gb); \
            CP16(sst + 2 * AMAT_BYTES + BMAT_BYTES + soff, pWl + gb); \
        } \
    } while (0)

    LOAD_CHUNK(0, 0);
    CP_COMMIT();
    if (nch > 1) { LOAD_CHUNK(1, 1); CP_COMMIT(); }

    int st = 0;
    for (int c = 0; c < nch; c++) {
        if (c + 2 < nch) {
            int s2 = st + 2; if (s2 >= 3) s2 -= 3;
            LOAD_CHUNK(s2, c + 2);
            CP_COMMIT();
            CP_WAIT2();
        } else if (c + 1 < nch) {
            CP_WAIT1();
        } else {
            CP_WAIT0();
        }
        __syncthreads();

        uint32_t base = sbase + st * STAGE_BYTES;
        uint32_t aAh = base, aAl = base + AMAT_BYTES;
        uint32_t aBh = base + 2 * AMAT_BYTES, aBl = aBh + BMAT_BYTES;

#pragma unroll
        for (int kk = 0; kk < 2; kk++) {
            int kch = kk * 2;
            uint32_t ahf[2][4], alf[2][4], bhf[2][4], blf[2][4];
#pragma unroll
            for (int mt = 0; mt < 2; mt++) {
                uint32_t ao = (uint32_t)(wm + mt * 16 + a_row) * ASTRIDE + (kch + a_hi) * 16;
                LDSM4(ahf[mt], aAh + ao);
                LDSM4(alf[mt], aAl + ao);
            }
#pragma unroll
            for (int np = 0; np < 2; np++) {
                uint32_t bo = (uint32_t)(wn + np * 16 + b_row) * ASTRIDE + (kch + b_hi) * 16;
                LDSM4(bhf[np], aBh + bo);
                LDSM4(blf[np], aBl + bo);
            }
#pragma unroll
            for (int mt = 0; mt < 2; mt++)
#pragma unroll
                for (int nt = 0; nt < 4; nt++) {
                    int np = nt >> 1, s = (nt & 1) * 2;
                    MMA_BF16(acc[mt][nt], ahf[mt], bhf[np][s], bhf[np][s + 1]);
                    MMA_BF16(acc[mt][nt], ahf[mt], blf[np][s], blf[np][s + 1]);
                    MMA_BF16(acc[mt][nt], alf[mt], bhf[np][s], bhf[np][s + 1]);
                }
        }
        __syncthreads();
        if (++st == 3) st = 0;
    }
#undef LOAD_CHUNK

#pragma unroll
    for (int mt = 0; mt < 2; mt++) {
        int r0 = bm + wm + mt * 16 + (lane >> 2);
#pragma unroll
        for (int nt = 0; nt < 4; nt++) {
            int cl = wn + nt * 8 + (lane & 3) * 2;
            float bz0 = bsm[cl], bz1 = bsm[cl + 1];
            float2 v0, v1;
            v0.x = acc[mt][nt][0] + bz0;  v0.y = acc[mt][nt][1] + bz1;
            v1.x = acc[mt][nt][2] + bz0;  v1.y = acc[mt][nt][3] + bz1;
            *(float2*)(C + (size_t)r0 * Nc + bn + cl)       = v0;
            *(float2*)(C + (size_t)(r0 + 8) * Nc + bn + cl) = v1;
        }
    }
}

// ===== layer3 fused: H(B,256) -> expand inline -> @W3(3584,10) + bias -> log_softmax =====
#define L3_ROWS 64
__global__ __launch_bounds__(256)
void layer3_fused_kernel(const float* __restrict__ H, const float* __restrict__ W3,
                         const float* __restrict__ bias, float* __restrict__ out) {
    __shared__ float Hs[L3_ROWS * 33];
    __shared__ float Wm[32 * 10];
    __shared__ float Wsp[32 * 13 * 10];
    __shared__ float bs[10];
    int t = threadIdx.x;
    int r0 = blockIdx.x * L3_ROWS;
    int rl = t >> 2, sub = t & 3;
    if (t < 10) bs[t] = bias[t];

    float acc[10];
#pragma unroll
    for (int o = 0; o < 10; o++) acc[o] = 0.f;

    for (int i0 = 0; i0 < HID; i0 += 32) {
        __syncthreads();
        for (int idx = t; idx < L3_ROWS * 32; idx += 256) {
            int row = idx >> 5, col = idx & 31;
            Hs[row * 33 + col] = H[(size_t)(r0 + row) * HID + i0 + col];
        }
        for (int idx = t; idx < 320; idx += 256)
            Wm[idx] = W3[(size_t)i0 * 10 + idx];
        for (int idx = t; idx < 4160; idx += 256)
            Wsp[idx] = W3[(size_t)(HID + i0 * 13) * 10 + idx];
        __syncthreads();

        for (int ii = sub; ii < 32; ii += 4) {
            float xv = Hs[rl * 33 + ii];
            float mishv, Bv[16];
            kan_basis(xv, mishv, Bv);
            const float* wm  = &Wm[ii * 10];
            const float* wsp = &Wsp[ii * 130];
#pragma unroll
            for (int o = 0; o < 10; o++) acc[o] = fmaf(mishv, wm[o], acc[o]);
#pragma unroll
            for (int g = 0; g < NCOEF; g++) {
                float bgv = Bv[g];
#pragma unroll
                for (int o = 0; o < 10; o++) acc[o] = fmaf(bgv, wsp[g * 10 + o], acc[o]);
            }
        }
    }

#pragma unroll
    for (int o = 0; o < 10; o++) {
        acc[o] += __shfl_xor_sync(0xFFFFFFFF, acc[o], 1);
        acc[o] += __shfl_xor_sync(0xFFFFFFFF, acc[o], 2);
    }
    if (sub == 0) {
#pragma unroll
        for (int o = 0; o < 10; o++) acc[o] += bs[o];
        float m = acc[0];
#pragma unroll
        for (int o = 1; o < 10; o++) m = fmaxf(m, acc[o]);
        float s = 0.f;
#pragma unroll
        for (int o = 0; o < 10; o++) s += expf(acc[o] - m);
        float ls = logf(s) + m;
        int row = r0 + rl;
#pragma unroll
        for (int o = 0; o < 10; o++) out[(size_t)row * 10 + o] = acc[o] - ls;
    }
}

// ================= host =================
extern "C" void kernel_launch(void* const* d_in, const int* in_sizes, int n_in,
                              void* d_out, int out_size) {
    const float* x     = (const float*)d_in[0];
    const float* coef1 = (const float*)d_in[1];
    const float* sb1   = (const float*)d_in[2];
    const float* sp1   = (const float*)d_in[3];
    const float* b1    = (const float*)d_in[4];
    const float* coef2 = (const float*)d_in[5];
    const float* sb2   = (const float*)d_in[6];
    const float* sp2   = (const float*)d_in[7];
    const float* b2    = (const float*)d_in[8];
    const float* coef3 = (const float*)d_in[9];
    const float* sb3   = (const float*)d_in[10];
    const float* sp3   = (const float*)d_in[11];
    const float* b3    = (const float*)d_in[12];
    float* out = (float*)d_out;

    float *H, *W3;
    __nv_bfloat16 *Ah, *Al, *Wh1, *Wl1, *Wh2, *Wl2;
    cudaGetSymbolAddress((void**)&H,   g_H);
    cudaGetSymbolAddress((void**)&Ah,  g_Ah);
    cudaGetSymbolAddress((void**)&Al,  g_Al);
    cudaGetSymbolAddress((void**)&Wh1, g_Wh1);
    cudaGetSymbolAddress((void**)&Wl1, g_Wl1);
    cudaGetSymbolAddress((void**)&Wh2, g_Wh2);
    cudaGetSymbolAddress((void**)&Wl2, g_Wl2);
    cudaGetSymbolAddress((void**)&W3,  g_W3);

    cudaFuncSetAttribute(gemm_kernel, cudaFuncAttributeMaxDynamicSharedMemorySize, SMEM_GEMM);

    // one-time stream/event setup (host resources only; no device memory)
    static cudaStream_t sB = nullptr;
    static cudaEvent_t ev0 = nullptr, evW1 = nullptr, evW2 = nullptr;
    if (!sB) {
        cudaStreamCreateWithFlags(&sB, cudaStreamNonBlocking);
        cudaEventCreateWithFlags(&ev0,  cudaEventDisableTiming);
        cudaEventCreateWithFlags(&evW1, cudaEventDisableTiming);
        cudaEventCreateWithFlags(&evW2, cudaEventDisableTiming);
    }

    dim3 g1(HID / 128, BATCH / 64);   // (2, 128) = 256 CTAs

    // ---- prologue packs forked to side stream; main chain serial on default stream ----
    cudaEventRecord(ev0, 0);
    cudaStreamWaitEvent(sB, ev0, 0);
    buildWt_kernel<<<(HID * KP1 + 255) / 256, 256, 0, sB>>>(coef1, sb1, sp1, Wh1, Wl1, IN1, HID, KP1);
    cudaEventRecord(evW1, sB);
    buildWt_kernel<<<(HID * K2 + 255) / 256, 256, 0, sB>>>(coef2, sb2, sp2, Wh2, Wl2, HID, HID, K2);
    buildW3_kernel<<<(K2 * OUT3 + 255) / 256, 256, 0, sB>>>(coef3, sb3, sp3, W3);
    cudaEventRecord(evW2, sB);

    expand49_kernel<<<BATCH / 4, 256>>>(x, Ah, Al);                          // overlaps buildWt1
    cudaStreamWaitEvent(0, evW1, 0);
    gemm_kernel<<<g1, 256, SMEM_GEMM>>>(Ah, Al, Wh1, Wl1, b1, H, KP1, HID);  // overlaps buildWt2/W3 tail
    expand256_kernel<<<BATCH, 256>>>(H, Ah, Al);
    cudaStreamWaitEvent(0, evW2, 0);
    gemm_kernel<<<g1, 256, SMEM_GEMM>>>(Ah, Al, Wh2, Wl2, b2, H, K2, HID);
    layer3_fused_kernel<<<BATCH / L3_ROWS, 256>>>(H, W3, b3, out);
}

// round 15
// speedup vs baseline: 1.8466x; 1.0069x over previous
#include <cuda_runtime.h>
#include <cuda_bf16.h>
#include <cstdint>
#include <math.h>

#define BATCH 8192
#define IN1   49
#define HID   256
#define NCOEF 13
#define KP1   704      // 49*14 = 686, padded to 64-multiple
#define K2    3584     // 256*14
#define OUT3  10

// ================= helpers (baseline PTX only: sm_80-era features) =================
__device__ __forceinline__ uint32_t smem_to_u32(const void* p) {
    uint32_t a;
    asm("{ .reg .u64 t; cvta.to.shared.u64 t, %1; cvt.u32.u64 %0, t; }" : "=r"(a) : "l"(p));
    return a;
}

#define CP16(dst, src) \
    asm volatile("cp.async.cg.shared.global [%0], [%1], 16;" :: "r"(dst), "l"(src) : "memory")
#define CP_COMMIT() asm volatile("cp.async.commit_group;" ::: "memory")
#define CP_WAIT2()  asm volatile("cp.async.wait_group 2;" ::: "memory")
#define CP_WAIT1()  asm volatile("cp.async.wait_group 1;" ::: "memory")
#define CP_WAIT0()  asm volatile("cp.async.wait_group 0;" ::: "memory")

#define LDSM4(r, addr) \
    asm volatile("ldmatrix.sync.aligned.m8n8.x4.shared.b16 {%0,%1,%2,%3}, [%4];" \
        : "=r"((r)[0]), "=r"((r)[1]), "=r"((r)[2]), "=r"((r)[3]) : "r"(addr))

#define MMA_BF16(d, a, b0, b1) \
    asm volatile("mma.sync.aligned.m16n8k16.row.col.f32.bf16.bf16.f32 " \
        "{%0,%1,%2,%3},{%4,%5,%6,%7},{%8,%9},{%0,%1,%2,%3};" \
        : "+f"((d)[0]), "+f"((d)[1]), "+f"((d)[2]), "+f"((d)[3]) \
        : "r"((a)[0]), "r"((a)[1]), "r"((a)[2]), "r"((a)[3]), "r"(b0), "r"(b1))

// ================= scratch =================
__device__ float         g_H [BATCH * HID];
__device__ __nv_bfloat16 g_Ah[(size_t)BATCH * K2];
__device__ __nv_bfloat16 g_Al[(size_t)BATCH * K2];
__device__ __nv_bfloat16 g_Wh1[HID * KP1];
__device__ __nv_bfloat16 g_Wl1[HID * KP1];
__device__ __nv_bfloat16 g_Wh2[HID * K2];
__device__ __nv_bfloat16 g_Wl2[HID * K2];
__device__ float         g_W3[K2 * OUT3];

// ================= shared KAN math =================
__device__ __forceinline__ void kan_basis(float xv, float& mishv, float* Bv) {
    float sp = fmaxf(xv, 0.f) + log1pf(expf(-fabsf(xv)));
    mishv = xv * tanhf(sp);
    const float h = 0.4f;
#pragma unroll
    for (int j = 0; j < 16; j++) {
        float t0 = -2.0f + h * (float)(j - 3);
        float t1 = -2.0f + h * (float)(j - 2);
        Bv[j] = (xv >= t0 && xv < t1) ? 1.0f : 0.0f;
    }
#pragma unroll
    for (int d = 1; d <= 3; d++) {
        float inv = 1.0f / (h * (float)d);
#pragma unroll
        for (int j = 0; j < 16 - 3; j++) {
            if (j < 16 - d) {
                float tj   = -2.0f + h * (float)(j - 3);
                float tjd1 = -2.0f + h * (float)(j - 3 + d + 1);
                Bv[j] = (xv - tj) * inv * Bv[j] + (tjd1 - xv) * inv * Bv[j + 1];
            }
        }
        if (d < 3) {
            for (int j = 13; j < 16 - d; j++) {
                float tj   = -2.0f + h * (float)(j - 3);
                float tjd1 = -2.0f + h * (float)(j - 3 + d + 1);
                Bv[j] = (xv - tj) * inv * Bv[j] + (tjd1 - xv) * inv * Bv[j + 1];
            }
        }
    }
}

__device__ __forceinline__ void split_hl(float v, __nv_bfloat16& hi, __nv_bfloat16& lo) {
    hi = __float2bfloat16(v);
    lo = __float2bfloat16(v - __bfloat162float(hi));
}

// ========== expand for in=256 (layer 2 input): 1 batch row per block ==========
__global__ __launch_bounds__(256)
void expand256_kernel(const float* __restrict__ H, __nv_bfloat16* __restrict__ Ah,
                      __nv_bfloat16* __restrict__ Al) {
    __shared__ __nv_bfloat16 sh[K2];
    __shared__ __nv_bfloat16 sl[K2];
    int b = blockIdx.x, i = threadIdx.x;
    float xv = H[b * HID + i];
    float mishv, Bv[16];
    kan_basis(xv, mishv, Bv);
    split_hl(mishv, sh[i], sl[i]);
    int off = HID + i * NCOEF;
#pragma unroll
    for (int g = 0; g < NCOEF; g++) split_hl(Bv[g], sh[off + g], sl[off + g]);
    __syncthreads();

    const uint4* s4h = (const uint4*)sh;
    const uint4* s4l = (const uint4*)sl;
    uint4* oh = (uint4*)(Ah + (size_t)b * K2);
    uint4* ol = (uint4*)(Al + (size_t)b * K2);
#pragma unroll
    for (int u = 0; u < 2; u++) {
        int t = u * 256 + i;
        if (t < 448) { oh[t] = s4h[t]; ol[t] = s4l[t]; }
    }
}

// ========== expand for layer 1: fused pool + basis + pad; 4 batch rows per block ==========
__global__ __launch_bounds__(256)
void expand49_kernel(const float* __restrict__ x, __nv_bfloat16* __restrict__ Ah,
                     __nv_bfloat16* __restrict__ Al) {
    __shared__ __nv_bfloat16 sh[4 * KP1];
    __shared__ __nv_bfloat16 sl[4 * KP1];
    int t = threadIdx.x;
    int b0 = blockIdx.x * 4;
    __nv_bfloat16 z = __float2bfloat16(0.f);

    if (t < 72) {
        int r = t / 18, c = 686 + (t - (t / 18) * 18);
        sh[r * KP1 + c] = z;
        sl[r * KP1 + c] = z;
    }

    if (t < 196) {
        int r = t / 49, i = t - r * 49;
        int b = b0 + r;
        int pr = i / 7, pc = i - pr * 7;
        const float* base = x + (size_t)b * 784 + pr * 4 * 28 + pc * 4;
        float s = 0.f;
#pragma unroll
        for (int k = 0; k < 4; k++) {
            float4 v = *(const float4*)(base + k * 28);
            s += v.x + v.y + v.z + v.w;
        }
        float xv = s * 0.0625f;
        float mishv, Bv[16];
        kan_basis(xv, mishv, Bv);
        __nv_bfloat16* rh = sh + r * KP1;
        __nv_bfloat16* rl = sl + r * KP1;
        split_hl(mishv, rh[i], rl[i]);
        int off = IN1 + i * NCOEF;
#pragma unroll
        for (int g = 0; g < NCOEF; g++) split_hl(Bv[g], rh[off + g], rl[off + g]);
    }
    __syncthreads();

    const uint4* s4h = (const uint4*)sh;
    const uint4* s4l = (const uint4*)sl;
    uint4* oh = (uint4*)(Ah + (size_t)b0 * KP1);
    uint4* ol = (uint4*)(Al + (size_t)b0 * KP1);
#pragma unroll
    for (int u = 0; u < 2; u++) {
        int w = u * 256 + t;
        if (w < 352) { oh[w] = s4h[w]; ol[w] = s4l[w]; }
    }
}

// ========== pack W^T (N rows, KP cols, K-major) as bf16 hi/lo ==========
__global__ void buildWt_kernel(const float* __restrict__ coef, const float* __restrict__ sb_,
                               const float* __restrict__ sp_, __nv_bfloat16* __restrict__ Wh,
                               __nv_bfloat16* __restrict__ Wl, int in, int out, int KP) {
    int idx = blockIdx.x * blockDim.x + threadIdx.x;
    if (idx >= out * KP) return;
    int n = idx / KP, k = idx - n * KP;
    float v = 0.f;
    if (k < in) {
        v = sb_[k * out + n];
    } else if (k < in * 14) {
        int q = k - in;
        int i = q / 13, g = q - i * 13;
        v = coef[((size_t)i * out + n) * 13 + g] * sp_[i * out + n];
    }
    __nv_bfloat16 hi, lo;
    split_hl(v, hi, lo);
    Wh[idx] = hi;
    Wl[idx] = lo;
}

// ========== pack layer-3 W (K rows, 10 cols) as fp32 ==========
__global__ void buildW3_kernel(const float* __restrict__ coef, const float* __restrict__ sb_,
                               const float* __restrict__ sp_, float* __restrict__ W) {
    int idx = blockIdx.x * blockDim.x + threadIdx.x;
    if (idx >= K2 * OUT3) return;
    int r = idx / OUT3, o = idx - r * OUT3;
    float v;
    if (r < HID) {
        v = sb_[r * OUT3 + o];
    } else {
        int q = r - HID;
        int i = q / 13, g = q - i * 13;
        v = coef[((size_t)i * OUT3 + o) * 13 + g] * sp_[i * OUT3 + o];
    }
    W[idx] = v;
}

// ================= HMMA GEMM (term-major MMA issue: RAW chains broken) =================
#define ASTRIDE     80
#define AMAT_BYTES  (64 * ASTRIDE)     // 5120
#define BMAT_BYTES  (128 * ASTRIDE)    // 10240
#define STAGE_BYTES (2 * AMAT_BYTES + 2 * BMAT_BYTES)   // 30720
#define SMEM_GEMM   (3 * STAGE_BYTES + 512)

__global__ __launch_bounds__(256, 2)
void gemm_kernel(const __nv_bfloat16* __restrict__ Ah, const __nv_bfloat16* __restrict__ Al,
                 const __nv_bfloat16* __restrict__ Wh, const __nv_bfloat16* __restrict__ Wl,
                 const float* __restrict__ bias, float* __restrict__ C, int K, int Nc) {
    extern __shared__ char smem[];
    uint32_t sbase = smem_to_u32(smem);
    float* bsm = (float*)(smem + 3 * STAGE_BYTES);
    int tid = threadIdx.x, lane = tid & 31, wid = tid >> 5;
    int bm = blockIdx.y * 64, bn = blockIdx.x * 128;
    if (tid < 128) bsm[tid] = bias[bn + tid];

    const size_t strideA = (size_t)K * 2;
    const char* pAh = (const char*)Ah;
    const char* pAl = (const char*)Al;
    const char* pWh = (const char*)Wh;
    const char* pWl = (const char*)Wl;

    float acc[2][4][4];
#pragma unroll
    for (int i = 0; i < 2; i++)
#pragma unroll
        for (int j = 0; j < 4; j++)
#pragma unroll
            for (int q = 0; q < 4; q++) acc[i][j][q] = 0.f;

    int wm = (wid & 1) * 32, wn = (wid >> 1) * 32;
    int a_row = lane & 15, a_hi = lane >> 4;
    int bg = lane >> 3;
    int b_row = ((bg >> 1) << 3) + (lane & 7);
    int b_hi = bg & 1;

    int nch = K >> 5;
    int rowA = tid >> 2, chA = tid & 3;
    uint32_t soffA = rowA * ASTRIDE + chA * 16;

#define LOAD_CHUNK(stage, c) do { \
        size_t kb = (size_t)(c) * 64; \
        uint32_t sst = sbase + (stage) * STAGE_BYTES; \
        size_t ga = (size_t)(bm + rowA) * strideA + kb + chA * 16; \
        CP16(sst + soffA,              pAh + ga); \
        CP16(sst + AMAT_BYTES + soffA, pAl + ga); \
        _Pragma("unroll") \
        for (int u = 0; u < 2; u++) { \
            int idx = u * 256 + tid; \
            int row = idx >> 2, ch = idx & 3; \
            uint32_t soff = row * ASTRIDE + ch * 16; \
            size_t gb = (size_t)(bn + row) * strideA + kb + ch * 16; \
            CP16(sst + 2 * AMAT_BYTES + soff,              pWh + gb); \
            CP16(sst + 2 * AMAT_BYTES + BMAT_BYTES + soff, pWl + gb); \
        } \
    } while (0)

    LOAD_CHUNK(0, 0);
    CP_COMMIT();
    if (nch > 1) { LOAD_CHUNK(1, 1); CP_COMMIT(); }

    int st = 0;
    for (int c = 0; c < nch; c++) {
        if (c + 2 < nch) {
            int s2 = st + 2; if (s2 >= 3) s2 -= 3;
            LOAD_CHUNK(s2, c + 2);
            CP_COMMIT();
            CP_WAIT2();
        } else if (c + 1 < nch) {
            CP_WAIT1();
        } else {
            CP_WAIT0();
        }
        __syncthreads();

        uint32_t base = sbase + st * STAGE_BYTES;
        uint32_t aAh = base, aAl = base + AMAT_BYTES;
        uint32_t aBh = base + 2 * AMAT_BYTES, aBl = aBh + BMAT_BYTES;

#pragma unroll
        for (int kk = 0; kk < 2; kk++) {
            int kch = kk * 2;
            uint32_t ahf[2][4], alf[2][4], bhf[2][4], blf[2][4];
#pragma unroll
            for (int mt = 0; mt < 2; mt++) {
                uint32_t ao = (uint32_t)(wm + mt * 16 + a_row) * ASTRIDE + (kch + a_hi) * 16;
                LDSM4(ahf[mt], aAh + ao);
                LDSM4(alf[mt], aAl + ao);
            }
#pragma unroll
            for (int np = 0; np < 2; np++) {
                uint32_t bo = (uint32_t)(wn + np * 16 + b_row) * ASTRIDE + (kch + b_hi) * 16;
                LDSM4(bhf[np], aBh + bo);
                LDSM4(blf[np], aBl + bo);
            }
            // term-major issue: 8 independent MMAs per term; each acc reuse is
            // separated by 8 instructions -> RAW latency hidden in-order.
#pragma unroll
            for (int mt = 0; mt < 2; mt++)
#pragma unroll
                for (int nt = 0; nt < 4; nt++) {
                    int np = nt >> 1, s = (nt & 1) * 2;
                    MMA_BF16(acc[mt][nt], ahf[mt], bhf[np][s], bhf[np][s + 1]);
                }
#pragma unroll
            for (int mt = 0; mt < 2; mt++)
#pragma unroll
                for (int nt = 0; nt < 4; nt++) {
                    int np = nt >> 1, s = (nt & 1) * 2;
                    MMA_BF16(acc[mt][nt], ahf[mt], blf[np][s], blf[np][s + 1]);
                }
#pragma unroll
            for (int mt = 0; mt < 2; mt++)
#pragma unroll
                for (int nt = 0; nt < 4; nt++) {
                    int np = nt >> 1, s = (nt & 1) * 2;
                    MMA_BF16(acc[mt][nt], alf[mt], bhf[np][s], bhf[np][s + 1]);
                }
        }
        __syncthreads();
        if (++st == 3) st = 0;
    }
#undef LOAD_CHUNK

#pragma unroll
    for (int mt = 0; mt < 2; mt++) {
        int r0 = bm + wm + mt * 16 + (lane >> 2);
#pragma unroll
        for (int nt = 0; nt < 4; nt++) {
            int cl = wn + nt * 8 + (lane & 3) * 2;
            float bz0 = bsm[cl], bz1 = bsm[cl + 1];
            float2 v0, v1;
            v0.x = acc[mt][nt][0] + bz0;  v0.y = acc[mt][nt][1] + bz1;
            v1.x = acc[mt][nt][2] + bz0;  v1.y = acc[mt][nt][3] + bz1;
            *(float2*)(C + (size_t)r0 * Nc + bn + cl)       = v0;
            *(float2*)(C + (size_t)(r0 + 8) * Nc + bn + cl) = v1;
        }
    }
}

// ===== layer3 fused: H(B,256) -> expand inline -> @W3(3584,10) + bias -> log_softmax =====
#define L3_ROWS 64
__global__ __launch_bounds__(256)
void layer3_fused_kernel(const float* __restrict__ H, const float* __restrict__ W3,
                         const float* __restrict__ bias, float* __restrict__ out) {
    __shared__ float Hs[L3_ROWS * 33];
    __shared__ float Wm[32 * 10];
    __shared__ float Wsp[32 * 13 * 10];
    __shared__ float bs[10];
    int t = threadIdx.x;
    int r0 = blockIdx.x * L3_ROWS;
    int rl = t >> 2, sub = t & 3;
    if (t < 10) bs[t] = bias[t];

    float acc[10];
#pragma unroll
    for (int o = 0; o < 10; o++) acc[o] = 0.f;

    for (int i0 = 0; i0 < HID; i0 += 32) {
        __syncthreads();
        for (int idx = t; idx < L3_ROWS * 32; idx += 256) {
            int row = idx >> 5, col = idx & 31;
            Hs[row * 33 + col] = H[(size_t)(r0 + row) * HID + i0 + col];
        }
        for (int idx = t; idx < 320; idx += 256)
            Wm[idx] = W3[(size_t)i0 * 10 + idx];
        for (int idx = t; idx < 4160; idx += 256)
            Wsp[idx] = W3[(size_t)(HID + i0 * 13) * 10 + idx];
        __syncthreads();

        for (int ii = sub; ii < 32; ii += 4) {
            float xv = Hs[rl * 33 + ii];
            float mishv, Bv[16];
            kan_basis(xv, mishv, Bv);
            const float* wm  = &Wm[ii * 10];
            const float* wsp = &Wsp[ii * 130];
#pragma unroll
            for (int o = 0; o < 10; o++) acc[o] = fmaf(mishv, wm[o], acc[o]);
#pragma unroll
            for (int g = 0; g < NCOEF; g++) {
                float bgv = Bv[g];
#pragma unroll
                for (int o = 0; o < 10; o++) acc[o] = fmaf(bgv, wsp[g * 10 + o], acc[o]);
            }
        }
    }

#pragma unroll
    for (int o = 0; o < 10; o++) {
        acc[o] += __shfl_xor_sync(0xFFFFFFFF, acc[o], 1);
        acc[o] += __shfl_xor_sync(0xFFFFFFFF, acc[o], 2);
    }
    if (sub == 0) {
#pragma unroll
        for (int o = 0; o < 10; o++) acc[o] += bs[o];
        float m = acc[0];
#pragma unroll
        for (int o = 1; o < 10; o++) m = fmaxf(m, acc[o]);
        float s = 0.f;
#pragma unroll
        for (int o = 0; o < 10; o++) s += expf(acc[o] - m);
        float ls = logf(s) + m;
        int row = r0 + rl;
#pragma unroll
        for (int o = 0; o < 10; o++) out[(size_t)row * 10 + o] = acc[o] - ls;
    }
}

// ================= host =================
extern "C" void kernel_launch(void* const* d_in, const int* in_sizes, int n_in,
                              void* d_out, int out_size) {
    const float* x     = (const float*)d_in[0];
    const float* coef1 = (const float*)d_in[1];
    const float* sb1   = (const float*)d_in[2];
    const float* sp1   = (const float*)d_in[3];
    const float* b1    = (const float*)d_in[4];
    const float* coef2 = (const float*)d_in[5];
    const float* sb2   = (const float*)d_in[6];
    const float* sp2   = (const float*)d_in[7];
    const float* b2    = (const float*)d_in[8];
    const float* coef3 = (const float*)d_in[9];
    const float* sb3   = (const float*)d_in[10];
    const float* sp3   = (const float*)d_in[11];
    const float* b3    = (const float*)d_in[12];
    float* out = (float*)d_out;

    float *H, *W3;
    __nv_bfloat16 *Ah, *Al, *Wh1, *Wl1, *Wh2, *Wl2;
    cudaGetSymbolAddress((void**)&H,   g_H);
    cudaGetSymbolAddress((void**)&Ah,  g_Ah);
    cudaGetSymbolAddress((void**)&Al,  g_Al);
    cudaGetSymbolAddress((void**)&Wh1, g_Wh1);
    cudaGetSymbolAddress((void**)&Wl1, g_Wl1);
    cudaGetSymbolAddress((void**)&Wh2, g_Wh2);
    cudaGetSymbolAddress((void**)&Wl2, g_Wl2);
    cudaGetSymbolAddress((void**)&W3,  g_W3);

    cudaFuncSetAttribute(gemm_kernel, cudaFuncAttributeMaxDynamicSharedMemorySize, SMEM_GEMM);

    // one-time stream/event setup (host resources only; no device memory)
    static cudaStream_t sB = nullptr;
    static cudaEvent_t ev0 = nullptr, evW1 = nullptr, evW2 = nullptr;
    if (!sB) {
        cudaStreamCreateWithFlags(&sB, cudaStreamNonBlocking);
        cudaEventCreateWithFlags(&ev0,  cudaEventDisableTiming);
        cudaEventCreateWithFlags(&evW1, cudaEventDisableTiming);
        cudaEventCreateWithFlags(&evW2, cudaEventDisableTiming);
    }

    dim3 g1(HID / 128, BATCH / 64);   // (2, 128) = 256 CTAs

    // ---- prologue packs forked to side stream; main chain serial on default stream ----
    cudaEventRecord(ev0, 0);
    cudaStreamWaitEvent(sB, ev0, 0);
    buildWt_kernel<<<(HID * KP1 + 255) / 256, 256, 0, sB>>>(coef1, sb1, sp1, Wh1, Wl1, IN1, HID, KP1);
    cudaEventRecord(evW1, sB);
    buildWt_kernel<<<(HID * K2 + 255) / 256, 256, 0, sB>>>(coef2, sb2, sp2, Wh2, Wl2, HID, HID, K2);
    buildW3_kernel<<<(K2 * OUT3 + 255) / 256, 256, 0, sB>>>(coef3, sb3, sp3, W3);
    cudaEventRecord(evW2, sB);

    expand49_kernel<<<BATCH / 4, 256>>>(x, Ah, Al);
    cudaStreamWaitEvent(0, evW1, 0);
    gemm_kernel<<<g1, 256, SMEM_GEMM>>>(Ah, Al, Wh1, Wl1, b1, H, KP1, HID);
    expand256_kernel<<<BATCH, 256>>>(H, Ah, Al);
    cudaStreamWaitEvent(0, evW2, 0);
    gemm_kernel<<<g1, 256, SMEM_GEMM>>>(Ah, Al, Wh2, Wl2, b2, H, K2, HID);
    layer3_fused_kernel<<<BATCH / L3_ROWS, 256>>>(H, W3, b3, out);
}

// round 16
// speedup vs baseline: 2.0492x; 1.1097x over previous
#include <cuda_runtime.h>
#include <cuda_bf16.h>
#include <cstdint>
#include <math.h>

#define BATCH 8192
#define IN1   49
#define HID   256
#define NCOEF 13
#define KP1   704      // 49*14 = 686, padded to 64-multiple
#define K2    3584     // 256*14
#define OUT3  10

// ================= helpers (baseline PTX only: sm_80-era features) =================
__device__ __forceinline__ uint32_t smem_to_u32(const void* p) {
    uint32_t a;
    asm("{ .reg .u64 t; cvta.to.shared.u64 t, %1; cvt.u32.u64 %0, t; }" : "=r"(a) : "l"(p));
    return a;
}

#define CP16(dst, src) \
    asm volatile("cp.async.cg.shared.global [%0], [%1], 16;" :: "r"(dst), "l"(src) : "memory")
#define CP_COMMIT() asm volatile("cp.async.commit_group;" ::: "memory")
#define CP_WAIT2()  asm volatile("cp.async.wait_group 2;" ::: "memory")
#define CP_WAIT1()  asm volatile("cp.async.wait_group 1;" ::: "memory")
#define CP_WAIT0()  asm volatile("cp.async.wait_group 0;" ::: "memory")

#define LDSM4(r, addr) \
    asm volatile("ldmatrix.sync.aligned.m8n8.x4.shared.b16 {%0,%1,%2,%3}, [%4];" \
        : "=r"((r)[0]), "=r"((r)[1]), "=r"((r)[2]), "=r"((r)[3]) : "r"(addr))

#define MMA_BF16(d, a, b0, b1) \
    asm volatile("mma.sync.aligned.m16n8k16.row.col.f32.bf16.bf16.f32 " \
        "{%0,%1,%2,%3},{%4,%5,%6,%7},{%8,%9},{%0,%1,%2,%3};" \
        : "+f"((d)[0]), "+f"((d)[1]), "+f"((d)[2]), "+f"((d)[3]) \
        : "r"((a)[0]), "r"((a)[1]), "r"((a)[2]), "r"((a)[3]), "r"(b0), "r"(b1))

// ================= scratch =================
__device__ float         g_H [BATCH * HID];
__device__ __nv_bfloat16 g_Ah[(size_t)BATCH * K2];
__device__ __nv_bfloat16 g_Al[(size_t)BATCH * K2];
__device__ __nv_bfloat16 g_Wh1[HID * KP1];
__device__ __nv_bfloat16 g_Wl1[HID * KP1];
__device__ __nv_bfloat16 g_Wh2[HID * K2];
__device__ __nv_bfloat16 g_Wl2[HID * K2];
__device__ float         g_W3[K2 * OUT3];

// ================= KAN math =================
__device__ __forceinline__ float mish_f(float xv) {
    float sp = fmaxf(xv, 0.f) + log1pf(expf(-fabsf(xv)));
    return xv * tanhf(sp);
}

// Closed-form uniform cubic B-spline: for x in cell c (knots t_j = -3.2 + 0.4*j),
// the only nonzero basis are B_{c-3..c} with the standard cubic pieces.
// w[k] is the value of basis index j = c - k. Caller guards 0 <= j <= 12.
__device__ __forceinline__ void kan_basis4(float xv, float* w, int& c) {
    float u  = (xv + 3.2f) * 2.5f;
    float fc = floorf(u);
    fc = fminf(fmaxf(fc, -1.f), 16.f);     // clamp (also tames NaN/inf)
    c = (int)fc;
    float t  = u - fc;
    float t2 = t * t, t3 = t2 * t;
    float omt = 1.f - t;
    const float s = 1.f / 6.f;
    w[0] = t3 * s;                                   // B_c
    w[1] = (1.f + 3.f * t + 3.f * t2 - 3.f * t3) * s; // B_{c-1}
    w[2] = (4.f - 6.f * t2 + 3.f * t3) * s;           // B_{c-2}
    w[3] = omt * omt * omt * s;                       // B_{c-3}
}

__device__ __forceinline__ void split_hl(float v, __nv_bfloat16& hi, __nv_bfloat16& lo) {
    hi = __float2bfloat16(v);
    lo = __float2bfloat16(v - __bfloat162float(hi));
}

// ========== expand for in=256 (layer 2 input): 1 batch row per block ==========
__global__ __launch_bounds__(256)
void expand256_kernel(const float* __restrict__ H, __nv_bfloat16* __restrict__ Ah,
                      __nv_bfloat16* __restrict__ Al) {
    __shared__ __nv_bfloat16 sh[K2];
    __shared__ __nv_bfloat16 sl[K2];
    int b = blockIdx.x, i = threadIdx.x;
    float xv = H[b * HID + i];
    split_hl(mish_f(xv), sh[i], sl[i]);

    float w[4]; int c;
    kan_basis4(xv, w, c);
    int off = HID + i * NCOEF;
    __nv_bfloat16 z = __float2bfloat16(0.f);
#pragma unroll
    for (int g = 0; g < NCOEF; g++) { sh[off + g] = z; sl[off + g] = z; }
#pragma unroll
    for (int k = 0; k < 4; k++) {
        int j = c - k;
        if ((unsigned)j <= 12u) split_hl(w[k], sh[off + j], sl[off + j]);
    }
    __syncthreads();

    const uint4* s4h = (const uint4*)sh;
    const uint4* s4l = (const uint4*)sl;
    uint4* oh = (uint4*)(Ah + (size_t)b * K2);
    uint4* ol = (uint4*)(Al + (size_t)b * K2);
#pragma unroll
    for (int u = 0; u < 2; u++) {
        int t = u * 256 + i;
        if (t < 448) { oh[t] = s4h[t]; ol[t] = s4l[t]; }
    }
}

// ========== expand for layer 1: fused pool + basis + pad; 4 batch rows per block ==========
__global__ __launch_bounds__(256)
void expand49_kernel(const float* __restrict__ x, __nv_bfloat16* __restrict__ Ah,
                     __nv_bfloat16* __restrict__ Al) {
    __shared__ __nv_bfloat16 sh[4 * KP1];
    __shared__ __nv_bfloat16 sl[4 * KP1];
    int t = threadIdx.x;
    int b0 = blockIdx.x * 4;
    __nv_bfloat16 z = __float2bfloat16(0.f);

    if (t < 72) {
        int r = t / 18, c = 686 + (t - (t / 18) * 18);
        sh[r * KP1 + c] = z;
        sl[r * KP1 + c] = z;
    }

    if (t < 196) {
        int r = t / 49, i = t - r * 49;
        int b = b0 + r;
        int pr = i / 7, pc = i - pr * 7;
        const float* base = x + (size_t)b * 784 + pr * 4 * 28 + pc * 4;
        float s = 0.f;
#pragma unroll
        for (int k = 0; k < 4; k++) {
            float4 v = *(const float4*)(base + k * 28);
            s += v.x + v.y + v.z + v.w;
        }
        float xv = s * 0.0625f;
        __nv_bfloat16* rh = sh + r * KP1;
        __nv_bfloat16* rl = sl + r * KP1;
        split_hl(mish_f(xv), rh[i], rl[i]);

        float w[4]; int c;
        kan_basis4(xv, w, c);
        int off = IN1 + i * NCOEF;
#pragma unroll
        for (int g = 0; g < NCOEF; g++) { rh[off + g] = z; rl[off + g] = z; }
#pragma unroll
        for (int k = 0; k < 4; k++) {
            int j = c - k;
            if ((unsigned)j <= 12u) split_hl(w[k], rh[off + j], rl[off + j]);
        }
    }
    __syncthreads();

    const uint4* s4h = (const uint4*)sh;
    const uint4* s4l = (const uint4*)sl;
    uint4* oh = (uint4*)(Ah + (size_t)b0 * KP1);
    uint4* ol = (uint4*)(Al + (size_t)b0 * KP1);
#pragma unroll
    for (int u = 0; u < 2; u++) {
        int w2 = u * 256 + t;
        if (w2 < 352) { oh[w2] = s4h[w2]; ol[w2] = s4l[w2]; }
    }
}

// ========== pack W^T (N rows, KP cols, K-major) as bf16 hi/lo ==========
__global__ void buildWt_kernel(const float* __restrict__ coef, const float* __restrict__ sb_,
                               const float* __restrict__ sp_, __nv_bfloat16* __restrict__ Wh,
                               __nv_bfloat16* __restrict__ Wl, int in, int out, int KP) {
    int idx = blockIdx.x * blockDim.x + threadIdx.x;
    if (idx >= out * KP) return;
    int n = idx / KP, k = idx - n * KP;
    float v = 0.f;
    if (k < in) {
        v = sb_[k * out + n];
    } else if (k < in * 14) {
        int q = k - in;
        int i = q / 13, g = q - i * 13;
        v = coef[((size_t)i * out + n) * 13 + g] * sp_[i * out + n];
    }
    __nv_bfloat16 hi, lo;
    split_hl(v, hi, lo);
    Wh[idx] = hi;
    Wl[idx] = lo;
}

// ========== pack layer-3 W (K rows, 10 cols) as fp32 ==========
__global__ void buildW3_kernel(const float* __restrict__ coef, const float* __restrict__ sb_,
                               const float* __restrict__ sp_, float* __restrict__ W) {
    int idx = blockIdx.x * blockDim.x + threadIdx.x;
    if (idx >= K2 * OUT3) return;
    int r = idx / OUT3, o = idx - r * OUT3;
    float v;
    if (r < HID) {
        v = sb_[r * OUT3 + o];
    } else {
        int q = r - HID;
        int i = q / 13, g = q - i * 13;
        v = coef[((size_t)i * OUT3 + o) * 13 + g] * sp_[i * OUT3 + o];
    }
    W[idx] = v;
}

// ================= HMMA GEMM (proven core) =================
#define ASTRIDE     80
#define AMAT_BYTES  (64 * ASTRIDE)     // 5120
#define BMAT_BYTES  (128 * ASTRIDE)    // 10240
#define STAGE_BYTES (2 * AMAT_BYTES + 2 * BMAT_BYTES)   // 30720
#define SMEM_GEMM   (3 * STAGE_BYTES + 512)

__global__ __launch_bounds__(256, 2)
void gemm_kernel(const __nv_bfloat16* __restrict__ Ah, const __nv_bfloat16* __restrict__ Al,
                 const __nv_bfloat16* __restrict__ Wh, const __nv_bfloat16* __restrict__ Wl,
                 const float* __restrict__ bias, float* __restrict__ C, int K, int Nc) {
    extern __shared__ char smem[];
    uint32_t sbase = smem_to_u32(smem);
    float* bsm = (float*)(smem + 3 * STAGE_BYTES);
    int tid = threadIdx.x, lane = tid & 31, wid = tid >> 5;
    int bm = blockIdx.y * 64, bn = blockIdx.x * 128;
    if (tid < 128) bsm[tid] = bias[bn + tid];

    const size_t strideA = (size_t)K * 2;
    const char* pAh = (const char*)Ah;
    const char* pAl = (const char*)Al;
    const char* pWh = (const char*)Wh;
    const char* pWl = (const char*)Wl;

    float acc[2][4][4];
#pragma unroll
    for (int i = 0; i < 2; i++)
#pragma unroll
        for (int j = 0; j < 4; j++)
#pragma unroll
            for (int q = 0; q < 4; q++) acc[i][j][q] = 0.f;

    int wm = (wid & 1) * 32, wn = (wid >> 1) * 32;
    int a_row = lane & 15, a_hi = lane >> 4;
    int bg = lane >> 3;
    int b_row = ((bg >> 1) << 3) + (lane & 7);
    int b_hi = bg & 1;

    int nch = K >> 5;
    int rowA = tid >> 2, chA = tid & 3;
    uint32_t soffA = rowA * ASTRIDE + chA * 16;

#define LOAD_CHUNK(stage, c) do { \
        size_t kb = (size_t)(c) * 64; \
        uint32_t sst = sbase + (stage) * STAGE_BYTES; \
        size_t ga = (size_t)(bm + rowA) * strideA + kb + chA * 16; \
        CP16(sst + soffA,              pAh + ga); \
        CP16(sst + AMAT_BYTES + soffA, pAl + ga); \
        _Pragma("unroll") \
        for (int u = 0; u < 2; u++) { \
            int idx = u * 256 + tid; \
            int row = idx >> 2, ch = idx & 3; \
            uint32_t soff = row * ASTRIDE + ch * 16; \
            size_t gb = (size_t)(bn + row) * strideA + kb + ch * 16; \
            CP16(sst + 2 * AMAT_BYTES + soff,              pWh + gb); \
            CP16(sst + 2 * AMAT_BYTES + BMAT_BYTES + soff, pWl + gb); \
        } \
    } while (0)

    LOAD_CHUNK(0, 0);
    CP_COMMIT();
    if (nch > 1) { LOAD_CHUNK(1, 1); CP_COMMIT(); }

    int st = 0;
    for (int c = 0; c < nch; c++) {
        if (c + 2 < nch) {
            int s2 = st + 2; if (s2 >= 3) s2 -= 3;
            LOAD_CHUNK(s2, c + 2);
            CP_COMMIT();
            CP_WAIT2();
        } else if (c + 1 < nch) {
            CP_WAIT1();
        } else {
            CP_WAIT0();
        }
        __syncthreads();

        uint32_t base = sbase + st * STAGE_BYTES;
        uint32_t aAh = base, aAl = base + AMAT_BYTES;
        uint32_t aBh = base + 2 * AMAT_BYTES, aBl = aBh + BMAT_BYTES;

#pragma unroll
        for (int kk = 0; kk < 2; kk++) {
            int kch = kk * 2;
            uint32_t ahf[2][4], alf[2][4], bhf[2][4], blf[2][4];
#pragma unroll
            for (int mt = 0; mt < 2; mt++) {
                uint32_t ao = (uint32_t)(wm + mt * 16 + a_row) * ASTRIDE + (kch + a_hi) * 16;
                LDSM4(ahf[mt], aAh + ao);
                LDSM4(alf[mt], aAl + ao);
            }
#pragma unroll
            for (int np = 0; np < 2; np++) {
                uint32_t bo = (uint32_t)(wn + np * 16 + b_row) * ASTRIDE + (kch + b_hi) * 16;
                LDSM4(bhf[np], aBh + bo);
                LDSM4(blf[np], aBl + bo);
            }
#pragma unroll
            for (int mt = 0; mt < 2; mt++)
#pragma unroll
                for (int nt = 0; nt < 4; nt++) {
                    int np = nt >> 1, s = (nt & 1) * 2;
                    MMA_BF16(acc[mt][nt], ahf[mt], bhf[np][s], bhf[np][s + 1]);
                }
#pragma unroll
            for (int mt = 0; mt < 2; mt++)
#pragma unroll
                for (int nt = 0; nt < 4; nt++) {
                    int np = nt >> 1, s = (nt & 1) * 2;
                    MMA_BF16(acc[mt][nt], ahf[mt], blf[np][s], blf[np][s + 1]);
                }
#pragma unroll
            for (int mt = 0; mt < 2; mt++)
#pragma unroll
                for (int nt = 0; nt < 4; nt++) {
                    int np = nt >> 1, s = (nt & 1) * 2;
                    MMA_BF16(acc[mt][nt], alf[mt], bhf[np][s], bhf[np][s + 1]);
                }
        }
        __syncthreads();
        if (++st == 3) st = 0;
    }
#undef LOAD_CHUNK

#pragma unroll
    for (int mt = 0; mt < 2; mt++) {
        int r0 = bm + wm + mt * 16 + (lane >> 2);
#pragma unroll
        for (int nt = 0; nt < 4; nt++) {
            int cl = wn + nt * 8 + (lane & 3) * 2;
            float bz0 = bsm[cl], bz1 = bsm[cl + 1];
            float2 v0, v1;
            v0.x = acc[mt][nt][0] + bz0;  v0.y = acc[mt][nt][1] + bz1;
            v1.x = acc[mt][nt][2] + bz0;  v1.y = acc[mt][nt][3] + bz1;
            *(float2*)(C + (size_t)r0 * Nc + bn + cl)       = v0;
            *(float2*)(C + (size_t)(r0 + 8) * Nc + bn + cl) = v1;
        }
    }
}

// ===== layer3 fused: H(B,256) -> 4-nonzero expand inline -> @W3 + bias -> log_softmax =====
#define L3_ROWS 64
__global__ __launch_bounds__(256)
void layer3_fused_kernel(const float* __restrict__ H, const float* __restrict__ W3,
                         const float* __restrict__ bias, float* __restrict__ out) {
    __shared__ float Hs[L3_ROWS * 33];
    __shared__ float Wm[32 * 10];
    __shared__ float Wsp[32 * 13 * 10];
    __shared__ float bs[10];
    int t = threadIdx.x;
    int r0 = blockIdx.x * L3_ROWS;
    int rl = t >> 2, sub = t & 3;
    if (t < 10) bs[t] = bias[t];

    float acc[10];
#pragma unroll
    for (int o = 0; o < 10; o++) acc[o] = 0.f;

    for (int i0 = 0; i0 < HID; i0 += 32) {
        __syncthreads();
        for (int idx = t; idx < L3_ROWS * 32; idx += 256) {
            int row = idx >> 5, col = idx & 31;
            Hs[row * 33 + col] = H[(size_t)(r0 + row) * HID + i0 + col];
        }
        for (int idx = t; idx < 320; idx += 256)
            Wm[idx] = W3[(size_t)i0 * 10 + idx];
        for (int idx = t; idx < 4160; idx += 256)
            Wsp[idx] = W3[(size_t)(HID + i0 * 13) * 10 + idx];
        __syncthreads();

        for (int ii = sub; ii < 32; ii += 4) {
            float xv = Hs[rl * 33 + ii];
            float mishv = mish_f(xv);
            float w[4]; int c;
            kan_basis4(xv, w, c);
            const float* wm  = &Wm[ii * 10];
            const float* wsp = &Wsp[ii * 130];
#pragma unroll
            for (int o = 0; o < 10; o++) acc[o] = fmaf(mishv, wm[o], acc[o]);
#pragma unroll
            for (int k = 0; k < 4; k++) {
                int j = c - k;
                if ((unsigned)j <= 12u) {
                    float bgv = w[k];
                    const float* wrow = wsp + j * 10;
#pragma unroll
                    for (int o = 0; o < 10; o++) acc[o] = fmaf(bgv, wrow[o], acc[o]);
                }
            }
        }
    }

#pragma unroll
    for (int o = 0; o < 10; o++) {
        acc[o] += __shfl_xor_sync(0xFFFFFFFF, acc[o], 1);
        acc[o] += __shfl_xor_sync(0xFFFFFFFF, acc[o], 2);
    }
    if (sub == 0) {
#pragma unroll
        for (int o = 0; o < 10; o++) acc[o] += bs[o];
        float m = acc[0];
#pragma unroll
        for (int o = 1; o < 10; o++) m = fmaxf(m, acc[o]);
        float s = 0.f;
#pragma unroll
        for (int o = 0; o < 10; o++) s += expf(acc[o] - m);
        float ls = logf(s) + m;
        int row = r0 + rl;
#pragma unroll
        for (int o = 0; o < 10; o++) out[(size_t)row * 10 + o] = acc[o] - ls;
    }
}

// ================= host =================
extern "C" void kernel_launch(void* const* d_in, const int* in_sizes, int n_in,
                              void* d_out, int out_size) {
    const float* x     = (const float*)d_in[0];
    const float* coef1 = (const float*)d_in[1];
    const float* sb1   = (const float*)d_in[2];
    const float* sp1   = (const float*)d_in[3];
    const float* b1    = (const float*)d_in[4];
    const float* coef2 = (const float*)d_in[5];
    const float* sb2   = (const float*)d_in[6];
    const float* sp2   = (const float*)d_in[7];
    const float* b2    = (const float*)d_in[8];
    const float* coef3 = (const float*)d_in[9];
    const float* sb3   = (const float*)d_in[10];
    const float* sp3   = (const float*)d_in[11];
    const float* b3    = (const float*)d_in[12];
    float* out = (float*)d_out;

    float *H, *W3;
    __nv_bfloat16 *Ah, *Al, *Wh1, *Wl1, *Wh2, *Wl2;
    cudaGetSymbolAddress((void**)&H,   g_H);
    cudaGetSymbolAddress((void**)&Ah,  g_Ah);
    cudaGetSymbolAddress((void**)&Al,  g_Al);
    cudaGetSymbolAddress((void**)&Wh1, g_Wh1);
    cudaGetSymbolAddress((void**)&Wl1, g_Wl1);
    cudaGetSymbolAddress((void**)&Wh2, g_Wh2);
    cudaGetSymbolAddress((void**)&Wl2, g_Wl2);
    cudaGetSymbolAddress((void**)&W3,  g_W3);

    cudaFuncSetAttribute(gemm_kernel, cudaFuncAttributeMaxDynamicSharedMemorySize, SMEM_GEMM);

    // one-time stream/event setup (host resources only; no device memory)
    static cudaStream_t sB = nullptr;
    static cudaEvent_t ev0 = nullptr, evW1 = nullptr, evW2 = nullptr;
    if (!sB) {
        cudaStreamCreateWithFlags(&sB, cudaStreamNonBlocking);
        cudaEventCreateWithFlags(&ev0,  cudaEventDisableTiming);
        cudaEventCreateWithFlags(&evW1, cudaEventDisableTiming);
        cudaEventCreateWithFlags(&evW2, cudaEventDisableTiming);
    }

    dim3 g1(HID / 128, BATCH / 64);   // (2, 128) = 256 CTAs

    // ---- prologue packs forked to side stream; main chain serial on default stream ----
    cudaEventRecord(ev0, 0);
    cudaStreamWaitEvent(sB, ev0, 0);
    buildWt_kernel<<<(HID * KP1 + 255) / 256, 256, 0, sB>>>(coef1, sb1, sp1, Wh1, Wl1, IN1, HID, KP1);
    cudaEventRecord(evW1, sB);
    buildWt_kernel<<<(HID * K2 + 255) / 256, 256, 0, sB>>>(coef2, sb2, sp2, Wh2, Wl2, HID, HID, K2);
    buildW3_kernel<<<(K2 * OUT3 + 255) / 256, 256, 0, sB>>>(coef3, sb3, sp3, W3);
    cudaEventRecord(evW2, sB);

    expand49_kernel<<<BATCH / 4, 256>>>(x, Ah, Al);
    cudaStreamWaitEvent(0, evW1, 0);
    gemm_kernel<<<g1, 256, SMEM_GEMM>>>(Ah, Al, Wh1, Wl1, b1, H, KP1, HID);
    expand256_kernel<<<BATCH, 256>>>(H, Ah, Al);
    cudaStreamWaitEvent(0, evW2, 0);
    gemm_kernel<<<g1, 256, SMEM_GEMM>>>(Ah, Al, Wh2, Wl2, b2, H, K2, HID);
    layer3_fused_kernel<<<BATCH / L3_ROWS, 256>>>(H, W3, b3, out);
}